// round 6
// baseline (speedup 1.0000x reference)
#include <cuda_runtime.h>
#include <math.h>

#define BB   32
#define SS   256
#define CC   1024
#define DW   768
#define HH   256
#define G4   1024          // 4*H
#define NTAG 9
#define WIH_STRIDE 2816

#define LSTM_SMEM_BYTES (16*256*16 + 256*8*4)   // ws4 64KB + hsm 8KB = 73728

// ---------------- scratch (static device globals; no allocations) ----------------
__device__ __align__(16) float g_v[BB*SS];                 // [b][s] broadcast scalar
__device__ __align__(16) float g_wsum[2*G4];               // [dir][gate] rowsum of Wih[:,768:]
__device__ __align__(16) float g_bias[2*G4];               // bih+bhh
__device__ __align__(16) float g_pre[(size_t)2*SS*BB*G4];  // [dir][t][b][g4]  (64 MB)
__device__ __align__(16) float g_hbuf[2*2*HH*BB];          // [dir][parity][j][b]
__device__ __align__(16) float g_hs[(size_t)2*SS*BB*HH];   // [dir][t][b][j]  (16 MB)
__device__ float g_loss_sum;
__device__ float g_loss_cnt;
__device__ unsigned g_cnt[8*64];                           // 8 sync groups, 256B apart

// ---------------- helpers ----------------
__device__ __forceinline__ float sigmoidf_(float x) { return 1.f / (1.f + __expf(-x)); }

__device__ __forceinline__ unsigned ldacq(const unsigned* p) {
    unsigned v;
    asm volatile("ld.acquire.gpu.u32 %0, [%1];" : "=r"(v) : "l"(p));
    return v;
}
__device__ __forceinline__ void redrel(unsigned* p, unsigned v) {
    asm volatile("red.release.gpu.add.u32 [%0], %1;" :: "l"(p), "r"(v) : "memory");
}
__device__ __forceinline__ unsigned f2tf(float x) {
    unsigned r;
    asm("cvt.rna.tf32.f32 %0, %1;" : "=r"(r) : "f"(x));
    return r;
}
__device__ __forceinline__ float4 tf4(float4 v) {
    float4 o;
    o.x = __uint_as_float(f2tf(v.x));
    o.y = __uint_as_float(f2tf(v.y));
    o.z = __uint_as_float(f2tf(v.z));
    o.w = __uint_as_float(f2tf(v.w));
    return o;
}
__device__ __forceinline__ void mma_tf32(float* c, const unsigned* a, const unsigned* b) {
    asm volatile(
        "mma.sync.aligned.m16n8k8.row.col.f32.tf32.tf32.f32 "
        "{%0,%1,%2,%3}, {%4,%5,%6,%7}, {%8,%9}, {%0,%1,%2,%3};"
        : "+f"(c[0]), "+f"(c[1]), "+f"(c[2]), "+f"(c[3])
        : "r"(a[0]), "r"(a[1]), "r"(a[2]), "r"(a[3]), "r"(b[0]), "r"(b[1]));
}

// ---------------- kernel 1: segment-mean scalar v[b,s] ----------------
__global__ void __launch_bounds__(256) prep_v_kernel(const float* __restrict__ char_embs,
                                                     const int*   __restrict__ spans) {
    int tid  = threadIdx.x;
    int lane = tid & 31;
    int token = blockIdx.x * 8 + (tid >> 5);
    int st = spans[token * 2 + 0];
    int en = spans[token * 2 + 1];
    float s = 0.f;
    if (st >= 0) {
        int b = token >> 8;
        for (int c = st; c <= en; ++c) {
            const float* p = char_embs + ((size_t)(b * CC + c)) * DW;
            float acc = 0.f;
            for (int d = lane; d < DW; d += 32) acc += p[d];
            s += acc;
        }
        #pragma unroll
        for (int off = 16; off; off >>= 1) s += __shfl_xor_sync(0xffffffffu, s, off);
        s /= (768.f * (float)(en - st + 1));
    }
    if (lane == 0) g_v[token] = (st >= 0) ? s : 0.f;
}

// ---------------- kernel 2: wsum + bias + zero accumulators/counters ----------------
__global__ void __launch_bounds__(256) prep_w_kernel(
        const float* __restrict__ WihF, const float* __restrict__ WihB,
        const float* __restrict__ bihF, const float* __restrict__ bhhF,
        const float* __restrict__ bihB, const float* __restrict__ bhhB) {
    int tid  = threadIdx.x;
    int lane = tid & 31;
    int row  = blockIdx.x * 8 + (tid >> 5);     // 0..2047
    int dir  = row >> 10;
    int g    = row & 1023;
    const float* W = dir ? WihB : WihF;
    const float* wp = W + (size_t)g * WIH_STRIDE;
    float s = 0.f;
    for (int k = DW + lane; k < WIH_STRIDE; k += 32) s += wp[k];
    #pragma unroll
    for (int off = 16; off; off >>= 1) s += __shfl_xor_sync(0xffffffffu, s, off);
    if (lane == 0) {
        g_wsum[row] = s;
        g_bias[row] = dir ? (bihB[g] + bhhB[g]) : (bihF[g] + bhhF[g]);
    }
    if (blockIdx.x == 0) {
        if (tid == 0) { g_loss_sum = 0.f; g_loss_cnt = 0.f; }
        for (int i = tid; i < 8 * 64; i += 256) g_cnt[i] = 0u;
    }
}

// ---------------- kernel 3: input projection GEMM (tf32 tensor cores) ----------------
// C[m,n] = word[m,:768] @ Wih_dir[g,:768]^T + v[m]*wsum[n] + bias[n]
// M=8192 (m=b*256+s), N=2048 (n=dir*1024+g), K=768.
// 128x128x32 CTA tile, 8 warps (2x4), each warp 64x32 via 4x4 m16n8k8 mma.
__global__ void __launch_bounds__(256, 1) gemm_pre_kernel(const float* __restrict__ A,
                                                          const float* __restrict__ WihF,
                                                          const float* __restrict__ WihB) {
    __shared__ float As[128 * 36];
    __shared__ float Bs[128 * 36];
    int tid  = threadIdx.x;
    int lane = tid & 31;
    int warp = tid >> 5;
    int wm = warp >> 2;            // 0..1
    int wn = warp & 3;             // 0..3
    int rowBase = blockIdx.y * 128;
    int nBase   = blockIdx.x * 128;

    int lrow = tid >> 3;           // 0..31
    int lq   = tid & 7;            // 0..7 -> col lq*4

    const float* aPtr[4];
    const float* bPtr[4];
    #pragma unroll
    for (int p = 0; p < 4; ++p) {
        int r = lrow + p * 32;
        aPtr[p] = A + (size_t)(rowBase + r) * DW + lq * 4;
        int n = nBase + r;
        const float* W = (n >= G4) ? WihB : WihF;
        bPtr[p] = W + (size_t)(n & 1023) * WIH_STRIDE + lq * 4;
    }

    float acc[4][4][4];
    #pragma unroll
    for (int mt = 0; mt < 4; ++mt)
        #pragma unroll
        for (int nt = 0; nt < 4; ++nt)
            #pragma unroll
            for (int q = 0; q < 4; ++q) acc[mt][nt][q] = 0.f;

    float4 ra[4], rb[4];
    #pragma unroll
    for (int p = 0; p < 4; ++p) {
        ra[p] = *(const float4*)aPtr[p];
        rb[p] = *(const float4*)bPtr[p];
    }

    for (int kt = 0; kt < DW; kt += 32) {
        if (kt) __syncthreads();
        #pragma unroll
        for (int p = 0; p < 4; ++p) {
            int r = lrow + p * 32;
            *(float4*)&As[r * 36 + lq * 4] = tf4(ra[p]);
            *(float4*)&Bs[r * 36 + lq * 4] = tf4(rb[p]);
        }
        __syncthreads();
        if (kt + 32 < DW) {
            #pragma unroll
            for (int p = 0; p < 4; ++p) {
                ra[p] = *(const float4*)(aPtr[p] + kt + 32);
                rb[p] = *(const float4*)(bPtr[p] + kt + 32);
            }
        }
        int q  = lane & 3;
        int gp = lane >> 2;
        #pragma unroll
        for (int kc = 0; kc < 32; kc += 8) {
            unsigned afr[4][4], bfr[4][2];
            #pragma unroll
            for (int mt = 0; mt < 4; ++mt) {
                int r = wm * 64 + mt * 16 + gp;
                afr[mt][0] = __float_as_uint(As[r * 36 + kc + q]);
                afr[mt][1] = __float_as_uint(As[(r + 8) * 36 + kc + q]);
                afr[mt][2] = __float_as_uint(As[r * 36 + kc + q + 4]);
                afr[mt][3] = __float_as_uint(As[(r + 8) * 36 + kc + q + 4]);
            }
            #pragma unroll
            for (int nt = 0; nt < 4; ++nt) {
                int c = wn * 32 + nt * 8 + gp;
                bfr[nt][0] = __float_as_uint(Bs[c * 36 + kc + q]);
                bfr[nt][1] = __float_as_uint(Bs[c * 36 + kc + q + 4]);
            }
            #pragma unroll
            for (int mt = 0; mt < 4; ++mt)
                #pragma unroll
                for (int nt = 0; nt < 4; ++nt)
                    mma_tf32(acc[mt][nt], afr[mt], bfr[nt]);
        }
    }

    // epilogue: b fixed per CTA (128-row M tile within one batch)
    int b = rowBase >> 8;
    #pragma unroll
    for (int mt = 0; mt < 4; ++mt) {
        int r0 = wm * 64 + mt * 16 + (lane >> 2);
        int m0 = rowBase + r0;
        float v0 = g_v[m0];
        float v1 = g_v[m0 + 8];
        int ss0 = m0 & 255;
        #pragma unroll
        for (int nt = 0; nt < 4; ++nt) {
            int n0  = nBase + wn * 32 + nt * 8 + 2 * (lane & 3);
            int dir = n0 >> 10;
            int g   = n0 & 1023;
            float2 w2  = *(const float2*)&g_wsum[n0];
            float2 bi2 = *(const float2*)&g_bias[n0];
            size_t base0 = (((size_t)dir * SS + ss0) * BB + b) * G4 + g;
            float2 o0 = make_float2(acc[mt][nt][0] + v0 * w2.x + bi2.x,
                                    acc[mt][nt][1] + v0 * w2.y + bi2.y);
            *(float2*)&g_pre[base0] = o0;
            size_t base1 = (((size_t)dir * SS + (ss0 + 8)) * BB + b) * G4 + g;
            float2 o1 = make_float2(acc[mt][nt][2] + v1 * w2.x + bi2.x,
                                    acc[mt][nt][3] + v1 * w2.y + bi2.y);
            *(float2*)&g_pre[base1] = o1;
        }
    }
}

// ---------------- kernel 4: bidirectional LSTM recurrence ----------------
// 128 CTAs = dir(2) x jslice(16; 16 j's each) x bslice(4; 8 b's each).
// Sync group = (dir, bslice): 16 CTAs, one aggregated counter per group
// (256B apart), 1 poller thread per CTA with nanosleep backoff.
// Thread (jl, bl) computes all 4 gates for its (j, b): 1024 FMA/step.
// Smem: ws4 [16 j][256 k] float4 = 64KB, hsm [256 k][8 b] = 8KB -> dynamic 72KB.
__global__ void __launch_bounds__(128) lstm_kernel(const float* __restrict__ WhhF,
                                                   const float* __restrict__ WhhB) {
    extern __shared__ float sm[];
    float4* ws4 = (float4*)sm;            // [jl][k] -> (Wi,Wf,Wg,Wo)  64KB
    float*  hsm = sm + 16 * 256 * 4;      // [k][bl]                   8KB

    int bid = blockIdx.x;
    int dir = bid >> 6;
    int js  = (bid >> 2) & 15;
    int bs  = bid & 3;
    int grp = dir * 4 + bs;
    int tid = threadIdx.x;
    int jl  = tid >> 3;      // 0..15
    int bl  = tid & 7;       // 0..7
    int j   = js * 16 + jl;
    int b   = bs * 8 + bl;

    const float* Whh = dir ? WhhB : WhhF;
    for (int i = tid; i < 16 * 256; i += 128) {
        int jj = i >> 8, k = i & 255;
        float4 w;
        w.x = Whh[(size_t)(0 * 256 + js * 16 + jj) * HH + k];
        w.y = Whh[(size_t)(1 * 256 + js * 16 + jj) * HH + k];
        w.z = Whh[(size_t)(2 * 256 + js * 16 + jj) * HH + k];
        w.w = Whh[(size_t)(3 * 256 + js * 16 + jj) * HH + k];
        ws4[jj * 256 + k] = w;
    }

    const float* preBase = g_pre + (size_t)dir * SS * BB * G4;
    float* hbD = g_hbuf + dir * 2 * HH * BB;
    unsigned* cp = &g_cnt[grp * 64];

    float c = 0.f;
    {
        int t0 = dir ? (SS - 1) : 0;
        const float* pp = preBase + ((size_t)t0 * BB + b) * G4 + j;
        float pi = pp[0], pf = pp[256], pg = pp[512], po = pp[768];

        for (int ts = 0; ts < SS; ++ts) {
            if (ts > 0) {
                if (tid == 0) {
                    unsigned tgt = 16u * (unsigned)ts;
                    while (ldacq(cp) < tgt) __nanosleep(64);
                }
                __syncthreads();
                // copy this CTA's 8-batch h slice (8KB) from L2, L1-bypassing
                const float* hg = hbD + (ts & 1) * (HH * BB);
                for (int i2 = tid; i2 < 512; i2 += 128) {
                    int k = i2 >> 1, half = i2 & 1;
                    float4 v = __ldcg((const float4*)(hg + k * 32 + bs * 8 + half * 4));
                    *(float4*)&hsm[k * 8 + half * 4] = v;
                }
                __syncthreads();
            }

            float ai = pi, af = pf, ag = pg, ao = po;
            if (ts + 1 < SS) {   // prefetch next step's pre, overlapped with matvec
                int tn = dir ? (SS - 2 - ts) : (ts + 1);
                const float* pn = preBase + ((size_t)tn * BB + b) * G4 + j;
                pi = pn[0]; pf = pn[256]; pg = pn[512]; po = pn[768];
            }

            if (ts > 0) {
                #pragma unroll 8
                for (int k = 0; k < HH; ++k) {
                    float hv = hsm[(k << 3) + bl];
                    float4 w = ws4[(jl << 8) + k];
                    ai = fmaf(w.x, hv, ai);
                    af = fmaf(w.y, hv, af);
                    ag = fmaf(w.z, hv, ag);
                    ao = fmaf(w.w, hv, ao);
                }
            }

            float iv = sigmoidf_(ai);
            float fv = sigmoidf_(af);
            float gv = tanhf(ag);
            float ov = sigmoidf_(ao);
            c = fv * c + iv * gv;
            float h = ov * tanhf(c);

            int t = dir ? (SS - 1 - ts) : ts;
            hbD[((ts + 1) & 1) * (HH * BB) + (j << 5) + b] = h;
            g_hs[(((size_t)dir * SS + t) * BB + b) * HH + j] = h;

            __threadfence();
            __syncthreads();
            if (tid == 0) redrel(cp, 1u);
        }
    }
}

// ---------------- kernel 5: emissions + NLL partial sums ----------------
__global__ void __launch_bounds__(256) emis_kernel(const int* __restrict__ labels,
                                                   const float* __restrict__ Wtag,
                                                   const float* __restrict__ btag) {
    __shared__ float wt[NTAG * 512];
    __shared__ float bt[NTAG];
    int tid = threadIdx.x;
    for (int i = tid; i < NTAG * 512; i += 256) wt[i] = Wtag[i];
    if (tid < NTAG) bt[tid] = btag[tid];
    __syncthreads();

    int idx = blockIdx.x * 256 + tid;      // 0..8191
    int b = idx >> 8, t = idx & 255;

    float acc[NTAG];
    #pragma unroll
    for (int q = 0; q < NTAG; ++q) acc[q] = bt[q];

    #pragma unroll
    for (int part = 0; part < 2; ++part) {
        const float* hp = g_hs + (((size_t)part * SS + t) * BB + b) * HH;
        for (int k4 = 0; k4 < HH; k4 += 4) {
            float4 h4 = *(const float4*)&hp[k4];
            #pragma unroll
            for (int q = 0; q < NTAG; ++q) {
                const float* w = &wt[q * 512 + part * HH + k4];
                acc[q] += h4.x * w[0] + h4.y * w[1] + h4.z * w[2] + h4.w * w[3];
            }
        }
    }

    int lab = labels[idx];
    float nll = 0.f, cnt = 0.f;
    if (lab != -100) {
        int lc = lab < 0 ? 0 : lab;
        float m = acc[0];
        #pragma unroll
        for (int q = 1; q < NTAG; ++q) m = fmaxf(m, acc[q]);
        float s = 0.f;
        #pragma unroll
        for (int q = 0; q < NTAG; ++q) s += __expf(acc[q] - m);
        nll = m + logf(s) - acc[lc];
        cnt = 1.f;
    }
    #pragma unroll
    for (int off = 16; off; off >>= 1) {
        nll += __shfl_xor_sync(0xffffffffu, nll, off);
        cnt += __shfl_xor_sync(0xffffffffu, cnt, off);
    }
    if ((tid & 31) == 0) {
        atomicAdd(&g_loss_sum, nll);
        atomicAdd(&g_loss_cnt, cnt);
    }
}

// ---------------- kernel 6: finalize ----------------
__global__ void finalize_kernel(float* out) {
    out[0] = g_loss_sum / fmaxf(g_loss_cnt, 1.f);
}

// ---------------- launch ----------------
extern "C" void kernel_launch(void* const* d_in, const int* in_sizes, int n_in,
                              void* d_out, int out_size) {
    const float* word_embs = (const float*)d_in[0];
    const float* char_embs = (const float*)d_in[1];
    const int*   spans     = (const int*)  d_in[2];
    const int*   labels    = (const int*)  d_in[3];
    const float* WihF      = (const float*)d_in[4];
    const float* WhhF      = (const float*)d_in[5];
    const float* bihF      = (const float*)d_in[6];
    const float* bhhF      = (const float*)d_in[7];
    const float* WihB      = (const float*)d_in[8];
    const float* WhhB      = (const float*)d_in[9];
    const float* bihB      = (const float*)d_in[10];
    const float* bhhB      = (const float*)d_in[11];
    const float* Wtag      = (const float*)d_in[12];
    const float* btag      = (const float*)d_in[13];
    float* out = (float*)d_out;

    cudaFuncSetAttribute(lstm_kernel, cudaFuncAttributeMaxDynamicSharedMemorySize, LSTM_SMEM_BYTES);

    prep_v_kernel<<<1024, 256>>>(char_embs, spans);
    prep_w_kernel<<<256, 256>>>(WihF, WihB, bihF, bhhF, bihB, bhhB);
    gemm_pre_kernel<<<dim3(16, 64), 256>>>(word_embs, WihF, WihB);
    lstm_kernel<<<128, 128, LSTM_SMEM_BYTES>>>(WhhF, WhhB);
    emis_kernel<<<32, 256>>>(labels, Wtag, btag);
    finalize_kernel<<<1, 1>>>(out);
}

// round 7
// speedup vs baseline: 1.2605x; 1.2605x over previous
#include <cuda_runtime.h>
#include <math.h>

#define BB   32
#define SS   256
#define CC   1024
#define DW   768
#define HH   256
#define G4   1024          // 4*H
#define NTAG 9
#define WIH_STRIDE 2816

// ---------------- scratch (static device globals; no allocations) ----------------
__device__ __align__(16) float g_v[BB*SS];                 // [b][s] broadcast scalar
__device__ __align__(16) float g_wsum[2*G4];               // [dir][gate] rowsum of Wih[:,768:]
__device__ __align__(16) float g_bias[2*G4];               // bih+bhh
__device__ __align__(16) float g_pre[(size_t)2*SS*BB*G4];  // [dir][t][b][g4]  (64 MB)
__device__ __align__(16) float g_hs[(size_t)2*SS*BB*HH];   // [dir][t][b][j]  (16 MB)
__device__ __align__(16) float g_wt[2*G4*HH];              // [dir][n'=j*4+gate][k] tf32-rounded (2 MB)
__device__ __align__(16) float g_hfrag[2*2*8192];          // [dir][parity][frag-linear 8192]
__device__ float g_loss_sum;
__device__ float g_loss_cnt;
__device__ unsigned g_flagp[2][64][32];                    // per-CTA flag, 128B padded

// ---------------- helpers ----------------
__device__ __forceinline__ float sigmoidf_(float x) { return 1.f / (1.f + __expf(-x)); }
__device__ __forceinline__ float tanh_fast(float x) {
    float e = __expf(-2.f * fabsf(x));
    float t = (1.f - e) / (1.f + e);
    return copysignf(t, x);
}
__device__ __forceinline__ unsigned ldacq(const unsigned* p) {
    unsigned v;
    asm volatile("ld.acquire.gpu.u32 %0, [%1];" : "=r"(v) : "l"(p));
    return v;
}
__device__ __forceinline__ void strel(unsigned* p, unsigned v) {
    asm volatile("st.release.gpu.u32 [%0], %1;" :: "l"(p), "r"(v));
}
__device__ __forceinline__ unsigned f2tf(float x) {
    unsigned r;
    asm("cvt.rna.tf32.f32 %0, %1;" : "=r"(r) : "f"(x));
    return r;
}
__device__ __forceinline__ float4 tf4(float4 v) {
    float4 o;
    o.x = __uint_as_float(f2tf(v.x));
    o.y = __uint_as_float(f2tf(v.y));
    o.z = __uint_as_float(f2tf(v.z));
    o.w = __uint_as_float(f2tf(v.w));
    return o;
}
__device__ __forceinline__ void mma_tf32(float* c, const unsigned* a, const unsigned* b) {
    asm volatile(
        "mma.sync.aligned.m16n8k8.row.col.f32.tf32.tf32.f32 "
        "{%0,%1,%2,%3}, {%4,%5,%6,%7}, {%8,%9}, {%0,%1,%2,%3};"
        : "+f"(c[0]), "+f"(c[1]), "+f"(c[2]), "+f"(c[3])
        : "r"(a[0]), "r"(a[1]), "r"(a[2]), "r"(a[3]), "r"(b[0]), "r"(b[1]));
}

// ---------------- kernel 1: segment-mean scalar v[b,s] ----------------
__global__ void __launch_bounds__(256) prep_v_kernel(const float* __restrict__ char_embs,
                                                     const int*   __restrict__ spans) {
    int tid  = threadIdx.x;
    int lane = tid & 31;
    int token = blockIdx.x * 8 + (tid >> 5);
    int st = spans[token * 2 + 0];
    int en = spans[token * 2 + 1];
    float s = 0.f;
    if (st >= 0) {
        int b = token >> 8;
        for (int c = st; c <= en; ++c) {
            const float* p = char_embs + ((size_t)(b * CC + c)) * DW;
            float acc = 0.f;
            for (int d = lane; d < DW; d += 32) acc += p[d];
            s += acc;
        }
        #pragma unroll
        for (int off = 16; off; off >>= 1) s += __shfl_xor_sync(0xffffffffu, s, off);
        s /= (768.f * (float)(en - st + 1));
    }
    if (lane == 0) g_v[token] = (st >= 0) ? s : 0.f;
}

// ---------------- kernel 2: wsum + bias + zero accumulators/flags ----------------
__global__ void __launch_bounds__(256) prep_w_kernel(
        const float* __restrict__ WihF, const float* __restrict__ WihB,
        const float* __restrict__ bihF, const float* __restrict__ bhhF,
        const float* __restrict__ bihB, const float* __restrict__ bhhB) {
    int tid  = threadIdx.x;
    int lane = tid & 31;
    int row  = blockIdx.x * 8 + (tid >> 5);     // 0..2047
    int dir  = row >> 10;
    int g    = row & 1023;
    const float* W = dir ? WihB : WihF;
    const float* wp = W + (size_t)g * WIH_STRIDE;
    float s = 0.f;
    for (int k = DW + lane; k < WIH_STRIDE; k += 32) s += wp[k];
    #pragma unroll
    for (int off = 16; off; off >>= 1) s += __shfl_xor_sync(0xffffffffu, s, off);
    if (lane == 0) {
        g_wsum[row] = s;
        g_bias[row] = dir ? (bihB[g] + bhhB[g]) : (bihF[g] + bhhF[g]);
    }
    if (blockIdx.x == 0) {
        if (tid == 0) { g_loss_sum = 0.f; g_loss_cnt = 0.f; }
        for (int i = tid; i < 2 * 64 * 32; i += 256) ((unsigned*)g_flagp)[i] = 0u;
    }
}

// ---------------- kernel 2b: reorder Whh -> g_wt[dir][n'=j*4+gate][k], tf32-rounded ----
__global__ void __launch_bounds__(256) prep_wt_kernel(const float* __restrict__ WhhF,
                                                      const float* __restrict__ WhhB) {
    int idx = blockIdx.x * 256 + threadIdx.x;   // 0 .. 524287
    int dir = idx >> 18;
    int r   = idx & 262143;
    int np  = r >> 8;          // n' 0..1023
    int k   = r & 255;
    int j = np >> 2, gate = np & 3;
    const float* W = dir ? WhhB : WhhF;
    float w = W[(size_t)(gate * 256 + j) * HH + k];
    g_wt[idx] = __uint_as_float(f2tf(w));
}

// ---------------- kernel 3: input projection GEMM (tf32 tensor cores) ----------------
// C[m,n] = word[m,:768] @ Wih_dir[g,:768]^T + v[m]*wsum[n] + bias[n]
// M=8192 (m=b*256+s), N=2048 (n=dir*1024+g), K=768.
__global__ void __launch_bounds__(256, 1) gemm_pre_kernel(const float* __restrict__ A,
                                                          const float* __restrict__ WihF,
                                                          const float* __restrict__ WihB) {
    __shared__ float As[128 * 36];
    __shared__ float Bs[128 * 36];
    int tid  = threadIdx.x;
    int lane = tid & 31;
    int warp = tid >> 5;
    int wm = warp >> 2;            // 0..1
    int wn = warp & 3;             // 0..3
    int rowBase = blockIdx.y * 128;
    int nBase   = blockIdx.x * 128;

    int lrow = tid >> 3;           // 0..31
    int lq   = tid & 7;            // 0..7 -> col lq*4

    const float* aPtr[4];
    const float* bPtr[4];
    #pragma unroll
    for (int p = 0; p < 4; ++p) {
        int r = lrow + p * 32;
        aPtr[p] = A + (size_t)(rowBase + r) * DW + lq * 4;
        int n = nBase + r;
        const float* W = (n >= G4) ? WihB : WihF;
        bPtr[p] = W + (size_t)(n & 1023) * WIH_STRIDE + lq * 4;
    }

    float acc[4][4][4];
    #pragma unroll
    for (int mt = 0; mt < 4; ++mt)
        #pragma unroll
        for (int nt = 0; nt < 4; ++nt)
            #pragma unroll
            for (int q = 0; q < 4; ++q) acc[mt][nt][q] = 0.f;

    float4 ra[4], rb[4];
    #pragma unroll
    for (int p = 0; p < 4; ++p) {
        ra[p] = *(const float4*)aPtr[p];
        rb[p] = *(const float4*)bPtr[p];
    }

    for (int kt = 0; kt < DW; kt += 32) {
        if (kt) __syncthreads();
        #pragma unroll
        for (int p = 0; p < 4; ++p) {
            int r = lrow + p * 32;
            *(float4*)&As[r * 36 + lq * 4] = tf4(ra[p]);
            *(float4*)&Bs[r * 36 + lq * 4] = tf4(rb[p]);
        }
        __syncthreads();
        if (kt + 32 < DW) {
            #pragma unroll
            for (int p = 0; p < 4; ++p) {
                ra[p] = *(const float4*)(aPtr[p] + kt + 32);
                rb[p] = *(const float4*)(bPtr[p] + kt + 32);
            }
        }
        int q  = lane & 3;
        int gp = lane >> 2;
        #pragma unroll
        for (int kc = 0; kc < 32; kc += 8) {
            unsigned afr[4][4], bfr[4][2];
            #pragma unroll
            for (int mt = 0; mt < 4; ++mt) {
                int r = wm * 64 + mt * 16 + gp;
                afr[mt][0] = __float_as_uint(As[r * 36 + kc + q]);
                afr[mt][1] = __float_as_uint(As[(r + 8) * 36 + kc + q]);
                afr[mt][2] = __float_as_uint(As[r * 36 + kc + q + 4]);
                afr[mt][3] = __float_as_uint(As[(r + 8) * 36 + kc + q + 4]);
            }
            #pragma unroll
            for (int nt = 0; nt < 4; ++nt) {
                int c = wn * 32 + nt * 8 + gp;
                bfr[nt][0] = __float_as_uint(Bs[c * 36 + kc + q]);
                bfr[nt][1] = __float_as_uint(Bs[c * 36 + kc + q + 4]);
            }
            #pragma unroll
            for (int mt = 0; mt < 4; ++mt)
                #pragma unroll
                for (int nt = 0; nt < 4; ++nt)
                    mma_tf32(acc[mt][nt], afr[mt], bfr[nt]);
        }
    }

    // epilogue: b fixed per CTA (128-row M tile within one batch)
    int b = rowBase >> 8;
    #pragma unroll
    for (int mt = 0; mt < 4; ++mt) {
        int r0 = wm * 64 + mt * 16 + (lane >> 2);
        int m0 = rowBase + r0;
        float v0 = g_v[m0];
        float v1 = g_v[m0 + 8];
        int ss0 = m0 & 255;
        #pragma unroll
        for (int nt = 0; nt < 4; ++nt) {
            int n0  = nBase + wn * 32 + nt * 8 + 2 * (lane & 3);
            int dir = n0 >> 10;
            int g   = n0 & 1023;
            float2 w2  = *(const float2*)&g_wsum[n0];
            float2 bi2 = *(const float2*)&g_bias[n0];
            size_t base0 = (((size_t)dir * SS + ss0) * BB + b) * G4 + g;
            float2 o0 = make_float2(acc[mt][nt][0] + v0 * w2.x + bi2.x,
                                    acc[mt][nt][1] + v0 * w2.y + bi2.y);
            *(float2*)&g_pre[base0] = o0;
            size_t base1 = (((size_t)dir * SS + (ss0 + 8)) * BB + b) * G4 + g;
            float2 o1 = make_float2(acc[mt][nt][2] + v1 * w2.x + bi2.x,
                                    acc[mt][nt][3] + v1 * w2.y + bi2.y);
            *(float2*)&g_pre[base1] = o1;
        }
    }
}

// ---------------- kernel 4: LSTM recurrence on tensor cores ----------------
// 128 CTAs = dir(2) x cg(64). CTA cg owns output cols' [cg*16, cg*16+16)
// = j in [cg*4, cg*4+4) x 4 gates. 4 warps split (kh, nh) = K-half x N-half.
// Per step: G[32b x 16col] = h[32 x 256] @ Wt^T via m16n8k8 tf32 mma.
// Whh fragments live in registers for the whole kernel. h is exchanged through
// g_hfrag in exact A-fragment order (one LDG.128 per fragment).
// Barrier: padded per-CTA flags, 1 release store, warp-parallel acquire polls.
__global__ void __launch_bounds__(128) lstm_kernel() {
    __shared__ float red[4][32][9];

    int bid  = blockIdx.x;
    int dir  = bid >> 6;
    int cg   = bid & 63;
    int tid  = threadIdx.x;
    int lane = tid & 31;
    int w    = tid >> 5;
    int kh   = w & 1;          // K half: k in [kh*128, kh*128+128)
    int nh   = w >> 1;         // N half: cols [nh*8, nh*8+8) of the 16

    // ---- load Whh B-fragments once (32 regs) ----
    unsigned bf0[16], bf1[16];
    {
        const float* Wt = g_wt + (size_t)dir * G4 * HH;
        int n = cg * 16 + nh * 8 + (lane >> 2);
        #pragma unroll
        for (int kt = 0; kt < 16; ++kt) {
            int k = kh * 128 + kt * 8 + (lane & 3);
            bf0[kt] = __float_as_uint(Wt[(size_t)n * HH + k]);
            bf1[kt] = __float_as_uint(Wt[(size_t)n * HH + k + 4]);
        }
    }

    // ---- cell identity: thread owns (b, jL): all 4 gates of one (b, j) ----
    int b  = tid >> 2;         // 0..31
    int jL = tid & 3;          // 0..3
    int j  = cg * 4 + jL;
    int mt_c = b >> 4;         // m-tile of this b
    int mr   = b & 15;         // row within m-tile

    // h fragment-store address for (b, j)
    int kin    = j & 7;
    int lane_s = ((mr & 7) << 2) | (kin & 3);
    int q_s    = ((kin >> 2) << 1) | (mr >> 3);
    int addr_h = (((j >> 3) * 2 + mt_c) * 32 + lane_s) * 4 + q_s;

    const float* preD  = g_pre   + (size_t)dir * SS * BB * G4;
    float*       hfD   = g_hfrag + dir * 2 * 8192;
    unsigned*    myfl  = &g_flagp[dir][cg][0];

    float c = 0.f;
    // prefetch pre-activations for step 0
    int t0 = dir ? (SS - 1) : 0;
    const float* pp0 = preD + ((size_t)t0 * BB + b) * G4 + j;
    float p0 = pp0[0], p1 = pp0[256], p2 = pp0[512], p3 = pp0[768];

    for (int ts = 0; ts < SS; ++ts) {
        int t = dir ? (SS - 1 - ts) : ts;

        // ---- barrier: wait until all 64 CTAs of this dir published step ts-1 ----
        if (ts > 0) {
            if (tid < 32) {
                const unsigned* fa = &g_flagp[dir][tid][0];
                const unsigned* fb = &g_flagp[dir][tid + 32][0];
                unsigned tg = (unsigned)ts;
                while (!__all_sync(0xffffffffu,
                        (unsigned)((ldacq(fa) >= tg) & (ldacq(fb) >= tg)))) { }
            }
            __syncthreads();
        }

        float pi = p0, pf = p1, pg = p2, po = p3;
        if (ts + 1 < SS) {   // prefetch next step's pre (off critical path)
            int tn = dir ? (SS - 2 - ts) : (ts + 1);
            const float* pn = preD + ((size_t)tn * BB + b) * G4 + j;
            p0 = pn[0]; p1 = pn[256]; p2 = pn[512]; p3 = pn[768];
        }

        // ---- matvec on tensor cores ----
        float acc0[4] = {0.f, 0.f, 0.f, 0.f};
        float acc1[4] = {0.f, 0.f, 0.f, 0.f};
        if (ts > 0) {
            const float4* hf = (const float4*)(hfD + (ts & 1) * 8192);
            #pragma unroll
            for (int kt = 0; kt < 16; ++kt) {
                int ktg = kh * 16 + kt;
                float4 a0 = __ldcg(hf + (ktg * 2 + 0) * 32 + lane);
                float4 a1 = __ldcg(hf + (ktg * 2 + 1) * 32 + lane);
                unsigned ar0[4] = {__float_as_uint(a0.x), __float_as_uint(a0.y),
                                   __float_as_uint(a0.z), __float_as_uint(a0.w)};
                unsigned ar1[4] = {__float_as_uint(a1.x), __float_as_uint(a1.y),
                                   __float_as_uint(a1.z), __float_as_uint(a1.w)};
                unsigned bb2[2] = {bf0[kt], bf1[kt]};
                mma_tf32(acc0, ar0, bb2);
                mma_tf32(acc1, ar1, bb2);
            }
        }

        // ---- K-reduction across the 2 K-half warps, via smem ----
        #pragma unroll
        for (int q = 0; q < 4; ++q) {
            red[w][lane][q]     = acc0[q];
            red[w][lane][4 + q] = acc1[q];
        }
        __syncthreads();

        float gv[4];
        #pragma unroll
        for (int g4 = 0; g4 < 4; ++g4) {
            int colL = jL * 4 + g4;
            int nh2 = colL >> 3, nc = colL & 7;
            int ln  = ((mr & 7) << 2) | (nc >> 1);
            int qi  = ((mr >> 3) << 1) | (nc & 1);
            int idx = mt_c * 4 + qi;
            gv[g4] = red[nh2 * 2 + 0][ln][idx] + red[nh2 * 2 + 1][ln][idx];
        }

        // ---- activations (fp32) ----
        float iv = sigmoidf_(gv[0] + pi);
        float fv = sigmoidf_(gv[1] + pf);
        float gg = tanh_fast(gv[2] + pg);
        float ov = sigmoidf_(gv[3] + po);
        c = fv * c + iv * gg;
        float h = ov * tanh_fast(c);

        // ---- publish h ----
        g_hs[(((size_t)dir * SS + t) * BB + b) * HH + j] = h;
        hfD[((ts + 1) & 1) * 8192 + addr_h] = __uint_as_float(f2tf(h));

        __threadfence();
        __syncthreads();
        if (tid == 0) strel(myfl, (unsigned)(ts + 1));
    }
}

// ---------------- kernel 5: emissions + NLL partial sums ----------------
__global__ void __launch_bounds__(256) emis_kernel(const int* __restrict__ labels,
                                                   const float* __restrict__ Wtag,
                                                   const float* __restrict__ btag) {
    __shared__ float wt[NTAG * 512];
    __shared__ float bt[NTAG];
    int tid = threadIdx.x;
    for (int i = tid; i < NTAG * 512; i += 256) wt[i] = Wtag[i];
    if (tid < NTAG) bt[tid] = btag[tid];
    __syncthreads();

    int idx = blockIdx.x * 256 + tid;      // 0..8191
    int b = idx >> 8, t = idx & 255;

    float acc[NTAG];
    #pragma unroll
    for (int q = 0; q < NTAG; ++q) acc[q] = bt[q];

    #pragma unroll
    for (int part = 0; part < 2; ++part) {
        const float* hp = g_hs + (((size_t)part * SS + t) * BB + b) * HH;
        for (int k4 = 0; k4 < HH; k4 += 4) {
            float4 h4 = *(const float4*)&hp[k4];
            #pragma unroll
            for (int q = 0; q < NTAG; ++q) {
                const float* w = &wt[q * 512 + part * HH + k4];
                acc[q] += h4.x * w[0] + h4.y * w[1] + h4.z * w[2] + h4.w * w[3];
            }
        }
    }

    int lab = labels[idx];
    float nll = 0.f, cnt = 0.f;
    if (lab != -100) {
        int lc = lab < 0 ? 0 : lab;
        float m = acc[0];
        #pragma unroll
        for (int q = 1; q < NTAG; ++q) m = fmaxf(m, acc[q]);
        float s = 0.f;
        #pragma unroll
        for (int q = 0; q < NTAG; ++q) s += __expf(acc[q] - m);
        nll = m + logf(s) - acc[lc];
        cnt = 1.f;
    }
    #pragma unroll
    for (int off = 16; off; off >>= 1) {
        nll += __shfl_xor_sync(0xffffffffu, nll, off);
        cnt += __shfl_xor_sync(0xffffffffu, cnt, off);
    }
    if ((tid & 31) == 0) {
        atomicAdd(&g_loss_sum, nll);
        atomicAdd(&g_loss_cnt, cnt);
    }
}

// ---------------- kernel 6: finalize ----------------
__global__ void finalize_kernel(float* out) {
    out[0] = g_loss_sum / fmaxf(g_loss_cnt, 1.f);
}

// ---------------- launch ----------------
extern "C" void kernel_launch(void* const* d_in, const int* in_sizes, int n_in,
                              void* d_out, int out_size) {
    const float* word_embs = (const float*)d_in[0];
    const float* char_embs = (const float*)d_in[1];
    const int*   spans     = (const int*)  d_in[2];
    const int*   labels    = (const int*)  d_in[3];
    const float* WihF      = (const float*)d_in[4];
    const float* WhhF      = (const float*)d_in[5];
    const float* bihF      = (const float*)d_in[6];
    const float* bhhF      = (const float*)d_in[7];
    const float* WihB      = (const float*)d_in[8];
    const float* WhhB      = (const float*)d_in[9];
    const float* bihB      = (const float*)d_in[10];
    const float* bhhB      = (const float*)d_in[11];
    const float* Wtag      = (const float*)d_in[12];
    const float* btag      = (const float*)d_in[13];
    float* out = (float*)d_out;

    prep_v_kernel<<<1024, 256>>>(char_embs, spans);
    prep_w_kernel<<<256, 256>>>(WihF, WihB, bihF, bhhF, bihB, bhhB);
    prep_wt_kernel<<<2048, 256>>>(WhhF, WhhB);
    gemm_pre_kernel<<<dim3(16, 64), 256>>>(word_embs, WihF, WihB);
    lstm_kernel<<<128, 128>>>();
    emis_kernel<<<32, 256>>>(labels, Wtag, btag);
    finalize_kernel<<<1, 1>>>(out);
}

// round 9
// speedup vs baseline: 1.4247x; 1.1303x over previous
#include <cuda_runtime.h>
#include <math.h>

#define BB   32
#define SS   256
#define CC   1024
#define DW   768
#define HH   256
#define G4   1024          // 4*H
#define NTAG 9
#define WIH_STRIDE 2816

// ---------------- scratch (static device globals; no allocations) ----------------
__device__ __align__(16) float g_v[BB*SS];                 // [b][s] broadcast scalar
__device__ __align__(16) float g_wsum[2*G4];               // [dir][gate] rowsum of Wih[:,768:]
__device__ __align__(16) float g_bias[2*G4];               // bih+bhh
__device__ __align__(16) float g_pre[(size_t)2*SS*BB*G4];  // [dir][t][b][g4]  (64 MB)
__device__ __align__(16) float g_hs[(size_t)2*SS*BB*HH];   // [dir][t][b][j]  (16 MB)
__device__ __align__(16) float g_wt[2*G4*HH];              // [dir][n'=j*4+gate][k] tf32 (2 MB)
__device__ __align__(16) float g_hfrag[2*2*8192];          // [dir][parity][frag-linear]
__device__ float g_loss_sum;
__device__ float g_loss_cnt;
__device__ unsigned g_flag2[2][16][32];                    // per-CTA flag, 128B padded

// ---------------- helpers ----------------
__device__ __forceinline__ float sigmoidf_(float x) { return 1.f / (1.f + __expf(-x)); }
__device__ __forceinline__ float tanh_fast(float x) {
    float e = __expf(-2.f * fabsf(x));
    float t = (1.f - e) / (1.f + e);
    return copysignf(t, x);
}
__device__ __forceinline__ unsigned ldacq(const unsigned* p) {
    unsigned v;
    asm volatile("ld.acquire.gpu.u32 %0, [%1];" : "=r"(v) : "l"(p));
    return v;
}
__device__ __forceinline__ void strel(unsigned* p, unsigned v) {
    asm volatile("st.release.gpu.u32 [%0], %1;" :: "l"(p), "r"(v));
}
__device__ __forceinline__ unsigned f2tf(float x) {
    unsigned r;
    asm("cvt.rna.tf32.f32 %0, %1;" : "=r"(r) : "f"(x));
    return r;
}
__device__ __forceinline__ float4 tf4(float4 v) {
    float4 o;
    o.x = __uint_as_float(f2tf(v.x));
    o.y = __uint_as_float(f2tf(v.y));
    o.z = __uint_as_float(f2tf(v.z));
    o.w = __uint_as_float(f2tf(v.w));
    return o;
}
__device__ __forceinline__ void mma_tf32(float* c, const unsigned* a, const unsigned* b) {
    asm volatile(
        "mma.sync.aligned.m16n8k8.row.col.f32.tf32.tf32.f32 "
        "{%0,%1,%2,%3}, {%4,%5,%6,%7}, {%8,%9}, {%0,%1,%2,%3};"
        : "+f"(c[0]), "+f"(c[1]), "+f"(c[2]), "+f"(c[3])
        : "r"(a[0]), "r"(a[1]), "r"(a[2]), "r"(a[3]), "r"(b[0]), "r"(b[1]));
}

// ---------------- kernel 1: segment-mean scalar v[b,s] ----------------
__global__ void __launch_bounds__(256) prep_v_kernel(const float* __restrict__ char_embs,
                                                     const int*   __restrict__ spans) {
    int tid  = threadIdx.x;
    int lane = tid & 31;
    int token = blockIdx.x * 8 + (tid >> 5);
    int st = spans[token * 2 + 0];
    int en = spans[token * 2 + 1];
    float s = 0.f;
    if (st >= 0) {
        int b = token >> 8;
        for (int c = st; c <= en; ++c) {
            const float* p = char_embs + ((size_t)(b * CC + c)) * DW;
            float acc = 0.f;
            for (int d = lane; d < DW; d += 32) acc += p[d];
            s += acc;
        }
        #pragma unroll
        for (int off = 16; off; off >>= 1) s += __shfl_xor_sync(0xffffffffu, s, off);
        s /= (768.f * (float)(en - st + 1));
    }
    if (lane == 0) g_v[token] = (st >= 0) ? s : 0.f;
}

// ---------------- kernel 2: wsum + bias + zero accumulators/flags ----------------
__global__ void __launch_bounds__(256) prep_w_kernel(
        const float* __restrict__ WihF, const float* __restrict__ WihB,
        const float* __restrict__ bihF, const float* __restrict__ bhhF,
        const float* __restrict__ bihB, const float* __restrict__ bhhB) {
    int tid  = threadIdx.x;
    int lane = tid & 31;
    int row  = blockIdx.x * 8 + (tid >> 5);     // 0..2047
    int dir  = row >> 10;
    int g    = row & 1023;
    const float* W = dir ? WihB : WihF;
    const float* wp = W + (size_t)g * WIH_STRIDE;
    float s = 0.f;
    for (int k = DW + lane; k < WIH_STRIDE; k += 32) s += wp[k];
    #pragma unroll
    for (int off = 16; off; off >>= 1) s += __shfl_xor_sync(0xffffffffu, s, off);
    if (lane == 0) {
        g_wsum[row] = s;
        g_bias[row] = dir ? (bihB[g] + bhhB[g]) : (bihF[g] + bhhF[g]);
    }
    if (blockIdx.x == 0) {
        if (tid == 0) { g_loss_sum = 0.f; g_loss_cnt = 0.f; }
        for (int i = tid; i < 2 * 16 * 32; i += 256) ((unsigned*)g_flag2)[i] = 0u;
    }
}

// ---------------- kernel 2b: reorder Whh -> g_wt[dir][n'=j*4+gate][k], tf32-rounded ----
__global__ void __launch_bounds__(256) prep_wt_kernel(const float* __restrict__ WhhF,
                                                      const float* __restrict__ WhhB) {
    int idx = blockIdx.x * 256 + threadIdx.x;   // 0 .. 524287
    int dir = idx >> 18;
    int r   = idx & 262143;
    int np  = r >> 8;          // n' 0..1023
    int k   = r & 255;
    int j = np >> 2, gate = np & 3;
    const float* W = dir ? WhhB : WhhF;
    float w = W[(size_t)(gate * 256 + j) * HH + k];
    g_wt[idx] = __uint_as_float(f2tf(w));
}

// ---------------- kernel 3: input projection GEMM (tf32 tensor cores) ----------------
__global__ void __launch_bounds__(256, 1) gemm_pre_kernel(const float* __restrict__ A,
                                                          const float* __restrict__ WihF,
                                                          const float* __restrict__ WihB) {
    __shared__ float As[128 * 36];
    __shared__ float Bs[128 * 36];
    int tid  = threadIdx.x;
    int lane = tid & 31;
    int warp = tid >> 5;
    int wm = warp >> 2;            // 0..1
    int wn = warp & 3;             // 0..3
    int rowBase = blockIdx.y * 128;
    int nBase   = blockIdx.x * 128;

    int lrow = tid >> 3;           // 0..31
    int lq   = tid & 7;            // 0..7 -> col lq*4

    const float* aPtr[4];
    const float* bPtr[4];
    #pragma unroll
    for (int p = 0; p < 4; ++p) {
        int r = lrow + p * 32;
        aPtr[p] = A + (size_t)(rowBase + r) * DW + lq * 4;
        int n = nBase + r;
        const float* W = (n >= G4) ? WihB : WihF;
        bPtr[p] = W + (size_t)(n & 1023) * WIH_STRIDE + lq * 4;
    }

    float acc[4][4][4];
    #pragma unroll
    for (int mt = 0; mt < 4; ++mt)
        #pragma unroll
        for (int nt = 0; nt < 4; ++nt)
            #pragma unroll
            for (int q = 0; q < 4; ++q) acc[mt][nt][q] = 0.f;

    float4 ra[4], rb[4];
    #pragma unroll
    for (int p = 0; p < 4; ++p) {
        ra[p] = *(const float4*)aPtr[p];
        rb[p] = *(const float4*)bPtr[p];
    }

    for (int kt = 0; kt < DW; kt += 32) {
        if (kt) __syncthreads();
        #pragma unroll
        for (int p = 0; p < 4; ++p) {
            int r = lrow + p * 32;
            *(float4*)&As[r * 36 + lq * 4] = tf4(ra[p]);
            *(float4*)&Bs[r * 36 + lq * 4] = tf4(rb[p]);
        }
        __syncthreads();
        if (kt + 32 < DW) {
            #pragma unroll
            for (int p = 0; p < 4; ++p) {
                ra[p] = *(const float4*)(aPtr[p] + kt + 32);
                rb[p] = *(const float4*)(bPtr[p] + kt + 32);
            }
        }
        int q  = lane & 3;
        int gp = lane >> 2;
        #pragma unroll
        for (int kc = 0; kc < 32; kc += 8) {
            unsigned afr[4][4], bfr[4][2];
            #pragma unroll
            for (int mt = 0; mt < 4; ++mt) {
                int r = wm * 64 + mt * 16 + gp;
                afr[mt][0] = __float_as_uint(As[r * 36 + kc + q]);
                afr[mt][1] = __float_as_uint(As[(r + 8) * 36 + kc + q]);
                afr[mt][2] = __float_as_uint(As[r * 36 + kc + q + 4]);
                afr[mt][3] = __float_as_uint(As[(r + 8) * 36 + kc + q + 4]);
            }
            #pragma unroll
            for (int nt = 0; nt < 4; ++nt) {
                int c = wn * 32 + nt * 8 + gp;
                bfr[nt][0] = __float_as_uint(Bs[c * 36 + kc + q]);
                bfr[nt][1] = __float_as_uint(Bs[c * 36 + kc + q + 4]);
            }
            #pragma unroll
            for (int mt = 0; mt < 4; ++mt)
                #pragma unroll
                for (int nt = 0; nt < 4; ++nt)
                    mma_tf32(acc[mt][nt], afr[mt], bfr[nt]);
        }
    }

    int b = rowBase >> 8;
    #pragma unroll
    for (int mt = 0; mt < 4; ++mt) {
        int r0 = wm * 64 + mt * 16 + (lane >> 2);
        int m0 = rowBase + r0;
        float v0 = g_v[m0];
        float v1 = g_v[m0 + 8];
        int ss0 = m0 & 255;
        #pragma unroll
        for (int nt = 0; nt < 4; ++nt) {
            int n0  = nBase + wn * 32 + nt * 8 + 2 * (lane & 3);
            int dir = n0 >> 10;
            int g   = n0 & 1023;
            float2 w2  = *(const float2*)&g_wsum[n0];
            float2 bi2 = *(const float2*)&g_bias[n0];
            size_t base0 = (((size_t)dir * SS + ss0) * BB + b) * G4 + g;
            float2 o0 = make_float2(acc[mt][nt][0] + v0 * w2.x + bi2.x,
                                    acc[mt][nt][1] + v0 * w2.y + bi2.y);
            *(float2*)&g_pre[base0] = o0;
            size_t base1 = (((size_t)dir * SS + (ss0 + 8)) * BB + b) * G4 + g;
            float2 o1 = make_float2(acc[mt][nt][2] + v1 * w2.x + bi2.x,
                                    acc[mt][nt][3] + v1 * w2.y + bi2.y);
            *(float2*)&g_pre[base1] = o1;
        }
    }
}

// ---------------- kernel 4: LSTM recurrence on tensor cores, 32 CTAs ----------------
// 32 CTAs = dir(2) x cg(16), 256 threads. CTA owns cols [cg*64, cg*64+64)
// (= j in [cg*16,+16) x 4 gates) for all 32 b. 8 warps = kh(2) x nq(4):
// warp computes G[32b x 16col] over its K-half via 64 m16n8k8 tf32 mma;
// Whh B-fragments register-resident. h exchanged via fragment-ordered global
// buffer (validated layout from R7). Warp-autonomous wait on 8 producer flags.
// WAR safety: each CTA's two K-half warp groups collectively wait on all 16
// CTAs; the post-reduction __syncthreads orders publishes after those waits.
__global__ void __launch_bounds__(256) lstm_kernel() {
    __shared__ float red2[2][64][33];   // [kh][col][b+pad]

    int bid  = blockIdx.x;
    int dir  = bid >> 4;
    int cg   = bid & 15;
    int tid  = threadIdx.x;
    int lane = tid & 31;
    int w    = tid >> 5;
    int kh   = w & 1;          // K half
    int nq   = w >> 1;         // 0..3: 16-column group

    // ---- Whh B-fragments, loaded once: 2 n-tiles x 16 kt x 2 regs ----
    unsigned bfr[2][16][2];
    {
        const float* Wt = g_wt + (size_t)dir * G4 * HH;
        #pragma unroll
        for (int nt = 0; nt < 2; ++nt) {
            int n = cg * 64 + nq * 16 + nt * 8 + (lane >> 2);
            const float* wrow = Wt + (size_t)n * HH + kh * 128 + (lane & 3);
            #pragma unroll
            for (int kt = 0; kt < 16; ++kt) {
                bfr[nt][kt][0] = __float_as_uint(wrow[kt * 8]);
                bfr[nt][kt][1] = __float_as_uint(wrow[kt * 8 + 4]);
            }
        }
    }

    // ---- cell identity: thread owns (b, jL) and (b, jL+8) ----
    int b  = tid >> 3;         // 0..31
    int jL = tid & 7;          // 0..7
    int j0c = cg * 16 + jL;
    int j1c = j0c + 8;
    int mt_c = b >> 4;
    int mr   = b & 15;
    int lane_s = ((mr & 7) << 2) | (jL & 3);
    int q_s    = ((jL >> 2) << 1) | (mr >> 3);
    // fragment float addresses (ktg = j>>3: cg*2 and cg*2+1)
    int addr0 = (((cg * 2 + 0) * 2 + mt_c) * 32 + lane_s) * 4 + q_s;
    int addr1 = (((cg * 2 + 1) * 2 + mt_c) * 32 + lane_s) * 4 + q_s;

    const float* preD = g_pre   + (size_t)dir * SS * BB * G4;
    float*       hfD  = g_hfrag + dir * 2 * 8192;
    unsigned*    myfl = &g_flag2[dir][cg][0];
    const unsigned* srcfl = &g_flag2[dir][kh * 8 + (lane & 7)][0];

    float c0 = 0.f, c1 = 0.f;
    float pr[8];
    {
        int t0 = dir ? (SS - 1) : 0;
        const float* pp = preD + ((size_t)t0 * BB + b) * G4;
        #pragma unroll
        for (int g = 0; g < 4; ++g) { pr[g] = pp[g * 256 + j0c]; pr[4 + g] = pp[g * 256 + j1c]; }
    }

    for (int ts = 0; ts < SS; ++ts) {
        int t = dir ? (SS - 1 - ts) : ts;

        // ---- warp-autonomous wait: 8 producer CTAs of this K-half ----
        if (ts > 0) {
            unsigned tg = (unsigned)ts;
            for (;;) {
                bool ok = true;
                if (lane < 8) ok = (ldacq(srcfl) >= tg);
                if (__ballot_sync(0xffffffffu, ok) == 0xffffffffu) break;
            }
        }

        // prefetch next step's pre-activations (off critical path)
        float np[8];
        if (ts + 1 < SS) {
            int tn = dir ? (SS - 2 - ts) : (ts + 1);
            const float* pn = preD + ((size_t)tn * BB + b) * G4;
            #pragma unroll
            for (int g = 0; g < 4; ++g) { np[g] = pn[g * 256 + j0c]; np[4 + g] = pn[g * 256 + j1c]; }
        }

        // ---- matvec on tensor cores ----
        float acc[2][2][4];
        #pragma unroll
        for (int mt = 0; mt < 2; ++mt)
            #pragma unroll
            for (int nt = 0; nt < 2; ++nt)
                #pragma unroll
                for (int q = 0; q < 4; ++q) acc[mt][nt][q] = 0.f;
        if (ts > 0) {
            const float4* hf = (const float4*)(hfD + (ts & 1) * 8192);
            #pragma unroll
            for (int kt = 0; kt < 16; ++kt) {
                int ktg = kh * 16 + kt;
                float4 a0 = __ldcg(hf + (ktg * 2 + 0) * 32 + lane);
                float4 a1 = __ldcg(hf + (ktg * 2 + 1) * 32 + lane);
                unsigned ar0[4] = {__float_as_uint(a0.x), __float_as_uint(a0.y),
                                   __float_as_uint(a0.z), __float_as_uint(a0.w)};
                unsigned ar1[4] = {__float_as_uint(a1.x), __float_as_uint(a1.y),
                                   __float_as_uint(a1.z), __float_as_uint(a1.w)};
                mma_tf32(acc[0][0], ar0, bfr[0][kt]);
                mma_tf32(acc[0][1], ar0, bfr[1][kt]);
                mma_tf32(acc[1][0], ar1, bfr[0][kt]);
                mma_tf32(acc[1][1], ar1, bfr[1][kt]);
            }
        }

        // ---- reduction across the 2 K-half warps via smem ----
        __syncthreads();   // red2 of previous step fully consumed
        #pragma unroll
        for (int mt = 0; mt < 2; ++mt)
            #pragma unroll
            for (int nt = 0; nt < 2; ++nt)
                #pragma unroll
                for (int q = 0; q < 4; ++q) {
                    int row = mt * 16 + (lane >> 2) + ((q & 2) ? 8 : 0);
                    int col = nq * 16 + nt * 8 + ((lane & 3) << 1) + (q & 1);
                    red2[kh][col][row] = acc[mt][nt][q];
                }
        __syncthreads();

        // ---- gates + activations for 2 cells ----
        float h0, h1;
        {
            float g0 = red2[0][jL * 4 + 0][b] + red2[1][jL * 4 + 0][b] + pr[0];
            float g1 = red2[0][jL * 4 + 1][b] + red2[1][jL * 4 + 1][b] + pr[1];
            float g2 = red2[0][jL * 4 + 2][b] + red2[1][jL * 4 + 2][b] + pr[2];
            float g3 = red2[0][jL * 4 + 3][b] + red2[1][jL * 4 + 3][b] + pr[3];
            c0 = sigmoidf_(g1) * c0 + sigmoidf_(g0) * tanh_fast(g2);
            h0 = sigmoidf_(g3) * tanh_fast(c0);
        }
        {
            int cb = 32 + jL * 4;
            float g0 = red2[0][cb + 0][b] + red2[1][cb + 0][b] + pr[4];
            float g1 = red2[0][cb + 1][b] + red2[1][cb + 1][b] + pr[5];
            float g2 = red2[0][cb + 2][b] + red2[1][cb + 2][b] + pr[6];
            float g3 = red2[0][cb + 3][b] + red2[1][cb + 3][b] + pr[7];
            c1 = sigmoidf_(g1) * c1 + sigmoidf_(g0) * tanh_fast(g2);
            h1 = sigmoidf_(g3) * tanh_fast(c1);
        }

        // ---- publish h ----
        float* hw = hfD + ((ts + 1) & 1) * 8192;
        hw[addr0] = __uint_as_float(f2tf(h0));
        hw[addr1] = __uint_as_float(f2tf(h1));
        float* ho = &g_hs[(((size_t)dir * SS + t) * BB + b) * HH];
        ho[j0c] = h0;
        ho[j1c] = h1;

        #pragma unroll
        for (int g = 0; g < 8; ++g) pr[g] = np[g];

        __syncthreads();                 // all stores issued before release
        if (tid == 0) strel(myfl, (unsigned)(ts + 1));
    }
}

// ---------------- kernel 5: emissions + NLL partial sums ----------------
__global__ void __launch_bounds__(256) emis_kernel(const int* __restrict__ labels,
                                                   const float* __restrict__ Wtag,
                                                   const float* __restrict__ btag) {
    __shared__ float wt[NTAG * 512];
    __shared__ float bt[NTAG];
    int tid = threadIdx.x;
    for (int i = tid; i < NTAG * 512; i += 256) wt[i] = Wtag[i];
    if (tid < NTAG) bt[tid] = btag[tid];
    __syncthreads();

    int idx = blockIdx.x * 256 + tid;      // 0..8191
    int b = idx >> 8, t = idx & 255;

    float acc[NTAG];
    #pragma unroll
    for (int q = 0; q < NTAG; ++q) acc[q] = bt[q];

    #pragma unroll
    for (int part = 0; part < 2; ++part) {
        const float* hp = g_hs + (((size_t)part * SS + t) * BB + b) * HH;
        for (int k4 = 0; k4 < HH; k4 += 4) {
            float4 h4 = *(const float4*)&hp[k4];
            #pragma unroll
            for (int q = 0; q < NTAG; ++q) {
                const float* w = &wt[q * 512 + part * HH + k4];
                acc[q] += h4.x * w[0] + h4.y * w[1] + h4.z * w[2] + h4.w * w[3];
            }
        }
    }

    int lab = labels[idx];
    float nll = 0.f, cnt = 0.f;
    if (lab != -100) {
        int lc = lab < 0 ? 0 : lab;
        float m = acc[0];
        #pragma unroll
        for (int q = 1; q < NTAG; ++q) m = fmaxf(m, acc[q]);
        float s = 0.f;
        #pragma unroll
        for (int q = 0; q < NTAG; ++q) s += __expf(acc[q] - m);
        nll = m + logf(s) - acc[lc];
        cnt = 1.f;
    }
    #pragma unroll
    for (int off = 16; off; off >>= 1) {
        nll += __shfl_xor_sync(0xffffffffu, nll, off);
        cnt += __shfl_xor_sync(0xffffffffu, cnt, off);
    }
    if ((tid & 31) == 0) {
        atomicAdd(&g_loss_sum, nll);
        atomicAdd(&g_loss_cnt, cnt);
    }
}

// ---------------- kernel 6: finalize ----------------
__global__ void finalize_kernel(float* out) {
    out[0] = g_loss_sum / fmaxf(g_loss_cnt, 1.f);
}

// ---------------- launch ----------------
extern "C" void kernel_launch(void* const* d_in, const int* in_sizes, int n_in,
                              void* d_out, int out_size) {
    const float* word_embs = (const float*)d_in[0];
    const float* char_embs = (const float*)d_in[1];
    const int*   spans     = (const int*)  d_in[2];
    const int*   labels    = (const int*)  d_in[3];
    const float* WihF      = (const float*)d_in[4];
    const float* WhhF      = (const float*)d_in[5];
    const float* bihF      = (const float*)d_in[6];
    const float* bhhF      = (const float*)d_in[7];
    const float* WihB      = (const float*)d_in[8];
    const float* WhhB      = (const float*)d_in[9];
    const float* bihB      = (const float*)d_in[10];
    const float* bhhB      = (const float*)d_in[11];
    const float* Wtag      = (const float*)d_in[12];
    const float* btag      = (const float*)d_in[13];
    float* out = (float*)d_out;

    prep_v_kernel<<<1024, 256>>>(char_embs, spans);
    prep_w_kernel<<<256, 256>>>(WihF, WihB, bihF, bhhF, bihB, bhhB);
    prep_wt_kernel<<<2048, 256>>>(WhhF, WhhB);
    gemm_pre_kernel<<<dim3(16, 64), 256>>>(word_embs, WihF, WihB);
    lstm_kernel<<<32, 256>>>();
    emis_kernel<<<32, 256>>>(labels, Wtag, btag);
    finalize_kernel<<<1, 1>>>(out);
}

// round 11
// speedup vs baseline: 1.9386x; 1.3607x over previous
#include <cuda_runtime.h>
#include <math.h>

#define BB   32
#define SS   256
#define CC   1024
#define DW   768
#define HH   256
#define G4   1024          // 4*H
#define NTAG 9
#define WIH_STRIDE 2816

#define FUSED_SMEM_BYTES (2 * 128 * 36 * 4)   // GEMM As+Bs = 36864 > LSTM red2 16896

// ---------------- scratch (static device globals; no allocations) ----------------
__device__ __align__(16) float g_v[BB*SS];                 // [b][s] broadcast scalar
__device__ __align__(16) float g_wsum[2*G4];               // [dir][gate] rowsum of Wih[:,768:]
__device__ __align__(16) float g_bias[2*G4];               // bih+bhh
__device__ __align__(16) float g_pre[(size_t)2*SS*BB*G4];  // [dir][t][b][g4]  (64 MB)
__device__ __align__(16) float g_hs[(size_t)2*SS*BB*HH];   // [dir][t][b][j]  (16 MB)
__device__ __align__(16) float g_wt[2*G4*HH];              // [dir][n'=j*4+gate][k] tf32 (2 MB)
__device__ __align__(16) float g_hfrag[2*2*8192];          // [dir][parity][frag-linear]
__device__ float g_loss_sum;
__device__ float g_loss_cnt;
__device__ unsigned g_flag2[2][16][32];                    // LSTM per-CTA flag, 128B padded
__device__ unsigned g_chunkcnt[16*32];                     // GEMM chunk counters, 128B padded

// ---------------- helpers ----------------
__device__ __forceinline__ float sigmoidf_(float x) { return 1.f / (1.f + __expf(-x)); }
__device__ __forceinline__ float tanh_fast(float x) {
    float e = __expf(-2.f * fabsf(x));
    float t = (1.f - e) / (1.f + e);
    return copysignf(t, x);
}
__device__ __forceinline__ unsigned ldacq(const unsigned* p) {
    unsigned v;
    asm volatile("ld.acquire.gpu.u32 %0, [%1];" : "=r"(v) : "l"(p));
    return v;
}
__device__ __forceinline__ void strel(unsigned* p, unsigned v) {
    asm volatile("st.release.gpu.u32 [%0], %1;" :: "l"(p), "r"(v));
}
__device__ __forceinline__ void redrel(unsigned* p, unsigned v) {
    asm volatile("red.release.gpu.add.u32 [%0], %1;" :: "l"(p), "r"(v) : "memory");
}
__device__ __forceinline__ unsigned f2tf(float x) {
    unsigned r;
    asm("cvt.rna.tf32.f32 %0, %1;" : "=r"(r) : "f"(x));
    return r;
}
__device__ __forceinline__ float4 tf4(float4 v) {
    float4 o;
    o.x = __uint_as_float(f2tf(v.x));
    o.y = __uint_as_float(f2tf(v.y));
    o.z = __uint_as_float(f2tf(v.z));
    o.w = __uint_as_float(f2tf(v.w));
    return o;
}
__device__ __forceinline__ void mma_tf32(float* c, const unsigned* a, const unsigned* b) {
    asm volatile(
        "mma.sync.aligned.m16n8k8.row.col.f32.tf32.tf32.f32 "
        "{%0,%1,%2,%3}, {%4,%5,%6,%7}, {%8,%9}, {%0,%1,%2,%3};"
        : "+f"(c[0]), "+f"(c[1]), "+f"(c[2]), "+f"(c[3])
        : "r"(a[0]), "r"(a[1]), "r"(a[2]), "r"(a[3]), "r"(b[0]), "r"(b[1]));
}
// warp-local wait until chunk ck's 64 producer CTAs have signalled
__device__ __forceinline__ void chunk_wait(int ck) {
    if ((threadIdx.x & 31) == 0) {
        const unsigned* p = &g_chunkcnt[ck * 32];
        while (ldacq(p) < 64u) { }
    }
    __syncwarp();
}

// ---------------- kernel 1: segment-mean scalar v[b,s] ----------------
__global__ void __launch_bounds__(256) prep_v_kernel(const float* __restrict__ char_embs,
                                                     const int*   __restrict__ spans) {
    int tid  = threadIdx.x;
    int lane = tid & 31;
    int token = blockIdx.x * 8 + (tid >> 5);
    int st = spans[token * 2 + 0];
    int en = spans[token * 2 + 1];
    float s = 0.f;
    if (st >= 0) {
        int b = token >> 8;
        for (int c = st; c <= en; ++c) {
            const float* p = char_embs + ((size_t)(b * CC + c)) * DW;
            float acc = 0.f;
            for (int d = lane; d < DW; d += 32) acc += p[d];
            s += acc;
        }
        #pragma unroll
        for (int off = 16; off; off >>= 1) s += __shfl_xor_sync(0xffffffffu, s, off);
        s /= (768.f * (float)(en - st + 1));
    }
    if (lane == 0) g_v[token] = (st >= 0) ? s : 0.f;
}

// ---------------- kernel 2: wsum + bias + zero accumulators/flags/counters ----------------
__global__ void __launch_bounds__(256) prep_w_kernel(
        const float* __restrict__ WihF, const float* __restrict__ WihB,
        const float* __restrict__ bihF, const float* __restrict__ bhhF,
        const float* __restrict__ bihB, const float* __restrict__ bhhB) {
    int tid  = threadIdx.x;
    int lane = tid & 31;
    int row  = blockIdx.x * 8 + (tid >> 5);     // 0..2047
    int dir  = row >> 10;
    int g    = row & 1023;
    const float* W = dir ? WihB : WihF;
    const float* wp = W + (size_t)g * WIH_STRIDE;
    float s = 0.f;
    for (int k = DW + lane; k < WIH_STRIDE; k += 32) s += wp[k];
    #pragma unroll
    for (int off = 16; off; off >>= 1) s += __shfl_xor_sync(0xffffffffu, s, off);
    if (lane == 0) {
        g_wsum[row] = s;
        g_bias[row] = dir ? (bihB[g] + bhhB[g]) : (bihF[g] + bhhF[g]);
    }
    if (blockIdx.x == 0) {
        if (tid == 0) { g_loss_sum = 0.f; g_loss_cnt = 0.f; }
        for (int i = tid; i < 2 * 16 * 32; i += 256) ((unsigned*)g_flag2)[i] = 0u;
        for (int i = tid; i < 16 * 32; i += 256) g_chunkcnt[i] = 0u;
    }
}

// ---------------- kernel 2b: reorder Whh -> g_wt[dir][n'=j*4+gate][k], tf32-rounded ----
__global__ void __launch_bounds__(256) prep_wt_kernel(const float* __restrict__ WhhF,
                                                      const float* __restrict__ WhhB) {
    int idx = blockIdx.x * 256 + threadIdx.x;   // 0 .. 524287
    int dir = idx >> 18;
    int r   = idx & 262143;
    int np  = r >> 8;          // n' 0..1023
    int k   = r & 255;
    int j = np >> 2, gate = np & 3;
    const float* W = dir ? WhhB : WhhF;
    float w = W[(size_t)(gate * 256 + j) * HH + k];
    g_wt[idx] = __uint_as_float(f2tf(w));
}

// ---------------- fused kernel: GEMM (blocks 32..1055) + LSTM (blocks 0..31) ----------------
// Shared memory is DYNAMIC and aliased per-path (each block runs exactly one path):
//   GEMM path: As[128*36] | Bs[128*36]  = 36864 B
//   LSTM path: red2[2][64][33]          = 16896 B
// GEMM: tf32 mma math, M-tile = 8 batches x 16 timesteps; 64 y-tiles = 16 chunks
// (seq order 0,15,1,14,...) x 4 batch-groups; x = 16 n-tiles. Each finished chunk
// release-counts g_chunkcnt (target 64 CTAs).
// LSTM: R9 structure; g_pre reads gated on chunk counters (16 waits per CTA);
// next-step pre prefetch before the h-flag wait; g_hs stores after the release.
__global__ void __launch_bounds__(256, 1) fused_kernel(const float* __restrict__ A,
                                                       const float* __restrict__ WihF,
                                                       const float* __restrict__ WihB) {
    extern __shared__ float smdyn[];

    if (blockIdx.x >= 32) {
        // =========================== GEMM path ===========================
        float* As = smdyn;               // [128*36]
        float* Bs = smdyn + 128 * 36;    // [128*36]
        int bid2 = blockIdx.x - 32;
        int gx = bid2 & 15;
        int gy = bid2 >> 4;            // 0..63
        int pos = gy >> 2;             // 0..15 position in chunk order
        int tb  = gy & 3;              // batch group: b in [tb*8, tb*8+8)
        int chunk = (pos & 1) ? (15 - (pos >> 1)) : (pos >> 1);

        int tid  = threadIdx.x;
        int lane = tid & 31;
        int warp = tid >> 5;
        int wm = warp >> 2;            // 0..1
        int wn = warp & 3;             // 0..3
        int nBase = gx * 128;

        int lrow = tid >> 3;           // 0..31
        int lq   = tid & 7;            // 0..7 -> col lq*4

        const float* aPtr[4];
        const float* bPtr[4];
        #pragma unroll
        for (int p = 0; p < 4; ++p) {
            int r  = lrow + p * 32;
            int rb = tb * 8 + (r & 7);
            int rs = chunk * 16 + (r >> 3);
            aPtr[p] = A + (size_t)(rb * 256 + rs) * DW + lq * 4;
            int n = nBase + r;
            const float* W = (n >= G4) ? WihB : WihF;
            bPtr[p] = W + (size_t)(n & 1023) * WIH_STRIDE + lq * 4;
        }

        float acc[4][4][4];
        #pragma unroll
        for (int mt = 0; mt < 4; ++mt)
            #pragma unroll
            for (int nt = 0; nt < 4; ++nt)
                #pragma unroll
                for (int q = 0; q < 4; ++q) acc[mt][nt][q] = 0.f;

        float4 ra[4], rb4[4];
        #pragma unroll
        for (int p = 0; p < 4; ++p) {
            ra[p]  = *(const float4*)aPtr[p];
            rb4[p] = *(const float4*)bPtr[p];
        }

        for (int kt = 0; kt < DW; kt += 32) {
            if (kt) __syncthreads();
            #pragma unroll
            for (int p = 0; p < 4; ++p) {
                int r = lrow + p * 32;
                *(float4*)&As[r * 36 + lq * 4] = tf4(ra[p]);
                *(float4*)&Bs[r * 36 + lq * 4] = tf4(rb4[p]);
            }
            __syncthreads();
            if (kt + 32 < DW) {
                #pragma unroll
                for (int p = 0; p < 4; ++p) {
                    ra[p]  = *(const float4*)(aPtr[p] + kt + 32);
                    rb4[p] = *(const float4*)(bPtr[p] + kt + 32);
                }
            }
            int q  = lane & 3;
            int gp = lane >> 2;
            #pragma unroll
            for (int kc = 0; kc < 32; kc += 8) {
                unsigned afr[4][4], bfr[4][2];
                #pragma unroll
                for (int mt = 0; mt < 4; ++mt) {
                    int r = wm * 64 + mt * 16 + gp;
                    afr[mt][0] = __float_as_uint(As[r * 36 + kc + q]);
                    afr[mt][1] = __float_as_uint(As[(r + 8) * 36 + kc + q]);
                    afr[mt][2] = __float_as_uint(As[r * 36 + kc + q + 4]);
                    afr[mt][3] = __float_as_uint(As[(r + 8) * 36 + kc + q + 4]);
                }
                #pragma unroll
                for (int nt = 0; nt < 4; ++nt) {
                    int c = wn * 32 + nt * 8 + gp;
                    bfr[nt][0] = __float_as_uint(Bs[c * 36 + kc + q]);
                    bfr[nt][1] = __float_as_uint(Bs[c * 36 + kc + q + 4]);
                }
                #pragma unroll
                for (int mt = 0; mt < 4; ++mt)
                    #pragma unroll
                    for (int nt = 0; nt < 4; ++nt)
                        mma_tf32(acc[mt][nt], afr[mt], bfr[nt]);
            }
        }

        // epilogue: fragment rows r0..r0+7 = 8 batches at fixed s; r0+8.. = same batches, s+1
        #pragma unroll
        for (int mt = 0; mt < 4; ++mt) {
            int base = wm * 64 + mt * 16;
            int s0 = chunk * 16 + (base >> 3);
            int bb = tb * 8 + (lane >> 2);
            float v0 = g_v[bb * 256 + s0];
            float v1 = g_v[bb * 256 + s0 + 1];
            #pragma unroll
            for (int nt = 0; nt < 4; ++nt) {
                int n0  = nBase + wn * 32 + nt * 8 + 2 * (lane & 3);
                int dir = n0 >> 10;
                int g   = n0 & 1023;
                float2 w2  = *(const float2*)&g_wsum[n0];
                float2 bi2 = *(const float2*)&g_bias[n0];
                size_t base0 = (((size_t)dir * SS + s0) * BB + bb) * G4 + g;
                float2 o0 = make_float2(acc[mt][nt][0] + v0 * w2.x + bi2.x,
                                        acc[mt][nt][1] + v0 * w2.y + bi2.y);
                *(float2*)&g_pre[base0] = o0;
                size_t base1 = (((size_t)dir * SS + (s0 + 1)) * BB + bb) * G4 + g;
                float2 o1 = make_float2(acc[mt][nt][2] + v1 * w2.x + bi2.x,
                                        acc[mt][nt][3] + v1 * w2.y + bi2.y);
                *(float2*)&g_pre[base1] = o1;
            }
        }

        __syncthreads();   // all epilogue stores issued (release below is cumulative)
        if (tid == 0) redrel(&g_chunkcnt[chunk * 32], 1u);
        return;
    }

    // =========================== LSTM path ===========================
    // red2[kh][col][b+pad] : kh*2112 + col*33 + b
    float* red2 = smdyn;

    int bid  = blockIdx.x;
    int dir  = bid >> 4;
    int cg   = bid & 15;
    int tid  = threadIdx.x;
    int lane = tid & 31;
    int w    = tid >> 5;
    int kh   = w & 1;          // K half
    int nq   = w >> 1;         // 0..3: 16-column group

    // ---- Whh B-fragments, loaded once (no chunk dependency) ----
    unsigned bfr[2][16][2];
    {
        const float* Wt = g_wt + (size_t)dir * G4 * HH;
        #pragma unroll
        for (int nt = 0; nt < 2; ++nt) {
            int n = cg * 64 + nq * 16 + nt * 8 + (lane >> 2);
            const float* wrow = Wt + (size_t)n * HH + kh * 128 + (lane & 3);
            #pragma unroll
            for (int kt = 0; kt < 16; ++kt) {
                bfr[nt][kt][0] = __float_as_uint(wrow[kt * 8]);
                bfr[nt][kt][1] = __float_as_uint(wrow[kt * 8 + 4]);
            }
        }
    }

    // ---- cell identity ----
    int b  = tid >> 3;         // 0..31
    int jL = tid & 7;          // 0..7
    int j0c = cg * 16 + jL;
    int j1c = j0c + 8;
    int mt_c = b >> 4;
    int mr   = b & 15;
    int lane_s = ((mr & 7) << 2) | (jL & 3);
    int q_s    = ((jL >> 2) << 1) | (mr >> 3);
    int addr0 = (((cg * 2 + 0) * 2 + mt_c) * 32 + lane_s) * 4 + q_s;
    int addr1 = (((cg * 2 + 1) * 2 + mt_c) * 32 + lane_s) * 4 + q_s;

    const float* preD = g_pre   + (size_t)dir * SS * BB * G4;
    float*       hfD  = g_hfrag + dir * 2 * 8192;
    unsigned*    myfl = &g_flag2[dir][cg][0];
    const unsigned* srcfl = &g_flag2[dir][kh * 8 + (lane & 7)][0];

    float c0 = 0.f, c1 = 0.f;
    float pr[8];
    {
        int t0 = dir ? (SS - 1) : 0;
        chunk_wait(t0 >> 4);            // gate first chunk (fwd: 0, bwd: 15)
        const float* pp = preD + ((size_t)t0 * BB + b) * G4;
        #pragma unroll
        for (int g = 0; g < 4; ++g) { pr[g] = pp[g * 256 + j0c]; pr[4 + g] = pp[g * 256 + j1c]; }
    }

    for (int ts = 0; ts < SS; ++ts) {
        int t  = dir ? (SS - 1 - ts) : ts;
        int tn = dir ? (SS - 2 - ts) : (ts + 1);

        // ---- gate next chunk of pre (once per 16 steps), then prefetch next pre ----
        if (ts + 1 < SS && (ts & 15) == 15) chunk_wait(tn >> 4);
        float np[8];
        if (ts + 1 < SS) {
            const float* pn = preD + ((size_t)tn * BB + b) * G4;
            #pragma unroll
            for (int g = 0; g < 4; ++g) { np[g] = pn[g * 256 + j0c]; np[4 + g] = pn[g * 256 + j1c]; }
        }

        // ---- warp-autonomous wait: 8 producer CTAs of this K-half ----
        if (ts > 0) {
            unsigned tg = (unsigned)ts;
            for (;;) {
                bool ok = true;
                if (lane < 8) ok = (ldacq(srcfl) >= tg);
                if (__ballot_sync(0xffffffffu, ok) == 0xffffffffu) break;
            }
        }

        // ---- matvec on tensor cores ----
        float acc[2][2][4];
        #pragma unroll
        for (int mt = 0; mt < 2; ++mt)
            #pragma unroll
            for (int nt = 0; nt < 2; ++nt)
                #pragma unroll
                for (int q = 0; q < 4; ++q) acc[mt][nt][q] = 0.f;
        if (ts > 0) {
            const float4* hf = (const float4*)(hfD + (ts & 1) * 8192);
            #pragma unroll
            for (int kt = 0; kt < 16; ++kt) {
                int ktg = kh * 16 + kt;
                float4 a0 = __ldcg(hf + (ktg * 2 + 0) * 32 + lane);
                float4 a1 = __ldcg(hf + (ktg * 2 + 1) * 32 + lane);
                unsigned ar0[4] = {__float_as_uint(a0.x), __float_as_uint(a0.y),
                                   __float_as_uint(a0.z), __float_as_uint(a0.w)};
                unsigned ar1[4] = {__float_as_uint(a1.x), __float_as_uint(a1.y),
                                   __float_as_uint(a1.z), __float_as_uint(a1.w)};
                mma_tf32(acc[0][0], ar0, bfr[0][kt]);
                mma_tf32(acc[0][1], ar0, bfr[1][kt]);
                mma_tf32(acc[1][0], ar1, bfr[0][kt]);
                mma_tf32(acc[1][1], ar1, bfr[1][kt]);
            }
        }

        // ---- reduction across the 2 K-half warps via smem ----
        __syncthreads();   // red2 of previous step fully consumed
        #pragma unroll
        for (int mt = 0; mt < 2; ++mt)
            #pragma unroll
            for (int nt = 0; nt < 2; ++nt)
                #pragma unroll
                for (int q = 0; q < 4; ++q) {
                    int row = mt * 16 + (lane >> 2) + ((q & 2) ? 8 : 0);
                    int col = nq * 16 + nt * 8 + ((lane & 3) << 1) + (q & 1);
                    red2[kh * 2112 + col * 33 + row] = acc[mt][nt][q];
                }
        __syncthreads();

        // ---- gates + activations for 2 cells ----
        float h0, h1;
        {
            float g0 = red2[(jL * 4 + 0) * 33 + b] + red2[2112 + (jL * 4 + 0) * 33 + b] + pr[0];
            float g1 = red2[(jL * 4 + 1) * 33 + b] + red2[2112 + (jL * 4 + 1) * 33 + b] + pr[1];
            float g2 = red2[(jL * 4 + 2) * 33 + b] + red2[2112 + (jL * 4 + 2) * 33 + b] + pr[2];
            float g3 = red2[(jL * 4 + 3) * 33 + b] + red2[2112 + (jL * 4 + 3) * 33 + b] + pr[3];
            c0 = sigmoidf_(g1) * c0 + sigmoidf_(g0) * tanh_fast(g2);
            h0 = sigmoidf_(g3) * tanh_fast(c0);
        }
        {
            int cb = 32 + jL * 4;
            float g0 = red2[(cb + 0) * 33 + b] + red2[2112 + (cb + 0) * 33 + b] + pr[4];
            float g1 = red2[(cb + 1) * 33 + b] + red2[2112 + (cb + 1) * 33 + b] + pr[5];
            float g2 = red2[(cb + 2) * 33 + b] + red2[2112 + (cb + 2) * 33 + b] + pr[6];
            float g3 = red2[(cb + 3) * 33 + b] + red2[2112 + (cb + 3) * 33 + b] + pr[7];
            c1 = sigmoidf_(g1) * c1 + sigmoidf_(g0) * tanh_fast(g2);
            h1 = sigmoidf_(g3) * tanh_fast(c1);
        }

        // ---- publish h fragments (critical path) ----
        float* hw = hfD + ((ts + 1) & 1) * 8192;
        hw[addr0] = __uint_as_float(f2tf(h0));
        hw[addr1] = __uint_as_float(f2tf(h1));

        __syncthreads();                 // all fragment stores issued before release
        if (tid == 0) strel(myfl, (unsigned)(ts + 1));

        // ---- off-critical-path: g_hs for emissions ----
        float* ho = &g_hs[(((size_t)dir * SS + t) * BB + b) * HH];
        ho[j0c] = h0;
        ho[j1c] = h1;

        #pragma unroll
        for (int g = 0; g < 8; ++g) pr[g] = np[g];
    }
}

// ---------------- kernel 5: emissions + NLL partial sums ----------------
__global__ void __launch_bounds__(256) emis_kernel(const int* __restrict__ labels,
                                                   const float* __restrict__ Wtag,
                                                   const float* __restrict__ btag) {
    __shared__ float wt[NTAG * 512];
    __shared__ float bt[NTAG];
    int tid = threadIdx.x;
    for (int i = tid; i < NTAG * 512; i += 256) wt[i] = Wtag[i];
    if (tid < NTAG) bt[tid] = btag[tid];
    __syncthreads();

    int idx = blockIdx.x * 256 + tid;      // 0..8191
    int b = idx >> 8, t = idx & 255;

    float acc[NTAG];
    #pragma unroll
    for (int q = 0; q < NTAG; ++q) acc[q] = bt[q];

    #pragma unroll
    for (int part = 0; part < 2; ++part) {
        const float* hp = g_hs + (((size_t)part * SS + t) * BB + b) * HH;
        for (int k4 = 0; k4 < HH; k4 += 4) {
            float4 h4 = *(const float4*)&hp[k4];
            #pragma unroll
            for (int q = 0; q < NTAG; ++q) {
                const float* w = &wt[q * 512 + part * HH + k4];
                acc[q] += h4.x * w[0] + h4.y * w[1] + h4.z * w[2] + h4.w * w[3];
            }
        }
    }

    int lab = labels[idx];
    float nll = 0.f, cnt = 0.f;
    if (lab != -100) {
        int lc = lab < 0 ? 0 : lab;
        float m = acc[0];
        #pragma unroll
        for (int q = 1; q < NTAG; ++q) m = fmaxf(m, acc[q]);
        float s = 0.f;
        #pragma unroll
        for (int q = 0; q < NTAG; ++q) s += __expf(acc[q] - m);
        nll = m + logf(s) - acc[lc];
        cnt = 1.f;
    }
    #pragma unroll
    for (int off = 16; off; off >>= 1) {
        nll += __shfl_xor_sync(0xffffffffu, nll, off);
        cnt += __shfl_xor_sync(0xffffffffu, cnt, off);
    }
    if ((tid & 31) == 0) {
        atomicAdd(&g_loss_sum, nll);
        atomicAdd(&g_loss_cnt, cnt);
    }
}

// ---------------- kernel 6: finalize ----------------
__global__ void finalize_kernel(float* out) {
    out[0] = g_loss_sum / fmaxf(g_loss_cnt, 1.f);
}

// ---------------- launch ----------------
extern "C" void kernel_launch(void* const* d_in, const int* in_sizes, int n_in,
                              void* d_out, int out_size) {
    const float* word_embs = (const float*)d_in[0];
    const float* char_embs = (const float*)d_in[1];
    const int*   spans     = (const int*)  d_in[2];
    const int*   labels    = (const int*)  d_in[3];
    const float* WihF      = (const float*)d_in[4];
    const float* WhhF      = (const float*)d_in[5];
    const float* bihF      = (const float*)d_in[6];
    const float* bhhF      = (const float*)d_in[7];
    const float* WihB      = (const float*)d_in[8];
    const float* WhhB      = (const float*)d_in[9];
    const float* bihB      = (const float*)d_in[10];
    const float* bhhB      = (const float*)d_in[11];
    const float* Wtag      = (const float*)d_in[12];
    const float* btag      = (const float*)d_in[13];
    float* out = (float*)d_out;

    cudaFuncSetAttribute(fused_kernel, cudaFuncAttributeMaxDynamicSharedMemorySize, FUSED_SMEM_BYTES);

    prep_v_kernel<<<1024, 256>>>(char_embs, spans);
    prep_w_kernel<<<256, 256>>>(WihF, WihB, bihF, bhhF, bihB, bhhB);
    prep_wt_kernel<<<2048, 256>>>(WhhF, WhhB);
    fused_kernel<<<1056, 256, FUSED_SMEM_BYTES>>>(word_embs, WihF, WihB);
    emis_kernel<<<32, 256>>>(labels, Wtag, btag);
    finalize_kernel<<<1, 1>>>(out);
}

// round 12
// speedup vs baseline: 2.0734x; 1.0695x over previous
#include <cuda_runtime.h>
#include <math.h>

#define BB   32
#define SS   256
#define CC   1024
#define DW   768
#define HH   256
#define G4   1024          // 4*H
#define NTAG 9
#define WIH_STRIDE 2816

// LSTM path: smB 32768 floats (128KB) + slab 8*272 floats; GEMM path: 36864 B. Max:
#define FUSED_SMEM_BYTES ((32768 + 8*272) * 4)   // 139776

// ---------------- scratch (static device globals; no allocations) ----------------
__device__ __align__(16) float g_v[BB*SS];                 // [b][s] broadcast scalar
__device__ __align__(16) float g_wsum[2*G4];               // [dir][gate] rowsum of Wih[:,768:]
__device__ __align__(16) float g_bias[2*G4];               // bih+bhh
__device__ __align__(16) float g_pre[(size_t)2*SS*BB*G4];  // [dir][t][b][g4]  (64 MB)
__device__ __align__(16) float g_hs[(size_t)2*SS*BB*HH];   // [dir][t][b][j]  (16 MB)
__device__ __align__(16) float g_wt[2*G4*HH];              // [dir][n'=j*4+gate][k] tf32 (2 MB)
__device__ __align__(16) float g_hfrag2[2*2*2*4096];       // [dir][bs][parity][frag words]
__device__ float g_loss_sum;
__device__ float g_loss_cnt;
__device__ unsigned g_flag3[2][2][8][32];                  // [dir][bs][producer js], 128B padded
__device__ unsigned g_chunkcnt[16*32];                     // GEMM chunk counters, 128B padded

// ---------------- helpers ----------------
__device__ __forceinline__ float sigmoidf_(float x) { return 1.f / (1.f + __expf(-x)); }
__device__ __forceinline__ float tanh_fast(float x) {
    float e = __expf(-2.f * fabsf(x));
    float t = (1.f - e) / (1.f + e);
    return copysignf(t, x);
}
__device__ __forceinline__ unsigned ldacq(const unsigned* p) {
    unsigned v;
    asm volatile("ld.acquire.gpu.u32 %0, [%1];" : "=r"(v) : "l"(p));
    return v;
}
__device__ __forceinline__ void strel(unsigned* p, unsigned v) {
    asm volatile("st.release.gpu.u32 [%0], %1;" :: "l"(p), "r"(v));
}
__device__ __forceinline__ void redrel(unsigned* p, unsigned v) {
    asm volatile("red.release.gpu.add.u32 [%0], %1;" :: "l"(p), "r"(v) : "memory");
}
__device__ __forceinline__ unsigned f2tf(float x) {
    unsigned r;
    asm("cvt.rna.tf32.f32 %0, %1;" : "=r"(r) : "f"(x));
    return r;
}
__device__ __forceinline__ float4 tf4(float4 v) {
    float4 o;
    o.x = __uint_as_float(f2tf(v.x));
    o.y = __uint_as_float(f2tf(v.y));
    o.z = __uint_as_float(f2tf(v.z));
    o.w = __uint_as_float(f2tf(v.w));
    return o;
}
__device__ __forceinline__ void mma_tf32(float* c, const unsigned* a, const unsigned* b) {
    asm volatile(
        "mma.sync.aligned.m16n8k8.row.col.f32.tf32.tf32.f32 "
        "{%0,%1,%2,%3}, {%4,%5,%6,%7}, {%8,%9}, {%0,%1,%2,%3};"
        : "+f"(c[0]), "+f"(c[1]), "+f"(c[2]), "+f"(c[3])
        : "r"(a[0]), "r"(a[1]), "r"(a[2]), "r"(a[3]), "r"(b[0]), "r"(b[1]));
}
// warp-local wait until chunk ck's 64 producer CTAs have signalled
__device__ __forceinline__ void chunk_wait(int ck) {
    if ((threadIdx.x & 31) == 0) {
        const unsigned* p = &g_chunkcnt[ck * 32];
        while (ldacq(p) < 64u) { }
    }
    __syncwarp();
}

// ---------------- kernel 1: segment-mean scalar v[b,s] ----------------
__global__ void __launch_bounds__(256) prep_v_kernel(const float* __restrict__ char_embs,
                                                     const int*   __restrict__ spans) {
    int tid  = threadIdx.x;
    int lane = tid & 31;
    int token = blockIdx.x * 8 + (tid >> 5);
    int st = spans[token * 2 + 0];
    int en = spans[token * 2 + 1];
    float s = 0.f;
    if (st >= 0) {
        int b = token >> 8;
        for (int c = st; c <= en; ++c) {
            const float* p = char_embs + ((size_t)(b * CC + c)) * DW;
            float acc = 0.f;
            for (int d = lane; d < DW; d += 32) acc += p[d];
            s += acc;
        }
        #pragma unroll
        for (int off = 16; off; off >>= 1) s += __shfl_xor_sync(0xffffffffu, s, off);
        s /= (768.f * (float)(en - st + 1));
    }
    if (lane == 0) g_v[token] = (st >= 0) ? s : 0.f;
}

// ---------------- kernel 2: wsum + bias + zero accumulators/flags/counters ----------------
__global__ void __launch_bounds__(256) prep_w_kernel(
        const float* __restrict__ WihF, const float* __restrict__ WihB,
        const float* __restrict__ bihF, const float* __restrict__ bhhF,
        const float* __restrict__ bihB, const float* __restrict__ bhhB) {
    int tid  = threadIdx.x;
    int lane = tid & 31;
    int row  = blockIdx.x * 8 + (tid >> 5);     // 0..2047
    int dir  = row >> 10;
    int g    = row & 1023;
    const float* W = dir ? WihB : WihF;
    const float* wp = W + (size_t)g * WIH_STRIDE;
    float s = 0.f;
    for (int k = DW + lane; k < WIH_STRIDE; k += 32) s += wp[k];
    #pragma unroll
    for (int off = 16; off; off >>= 1) s += __shfl_xor_sync(0xffffffffu, s, off);
    if (lane == 0) {
        g_wsum[row] = s;
        g_bias[row] = dir ? (bihB[g] + bhhB[g]) : (bihF[g] + bhhF[g]);
    }
    if (blockIdx.x == 0) {
        if (tid == 0) { g_loss_sum = 0.f; g_loss_cnt = 0.f; }
        for (int i = tid; i < 2 * 2 * 8 * 32; i += 256) ((unsigned*)g_flag3)[i] = 0u;
        for (int i = tid; i < 16 * 32; i += 256) g_chunkcnt[i] = 0u;
    }
}

// ---------------- kernel 2b: reorder Whh -> g_wt[dir][n'=j*4+gate][k], tf32-rounded ----
__global__ void __launch_bounds__(256) prep_wt_kernel(const float* __restrict__ WhhF,
                                                      const float* __restrict__ WhhB) {
    int idx = blockIdx.x * 256 + threadIdx.x;   // 0 .. 524287
    int dir = idx >> 18;
    int r   = idx & 262143;
    int np  = r >> 8;          // n' 0..1023
    int k   = r & 255;
    int j = np >> 2, gate = np & 3;
    const float* W = dir ? WhhB : WhhF;
    float w = W[(size_t)(gate * 256 + j) * HH + k];
    g_wt[idx] = __uint_as_float(f2tf(w));
}

// ---------------- fused kernel: GEMM (blocks 32..1055) + LSTM (blocks 0..31) ----------------
// Dynamic smem aliased per path:
//   GEMM: As[128*36] | Bs[128*36]  (36864 B)
//   LSTM: smB[32768] Whh B-fragments | slab[8*272] per-warp gate gather  (139776 B)
// LSTM topology (NEW): 32 CTAs = dir(2) x bs(2: 16 batches) x js(8: 32 j's).
// Each warp covers FULL K=256 for its 16 gate-cols (M=16 batches) -> no split-K
// reduction, no block syncs except one pre-release. Sync group = (dir,bs): 8 CTAs.
__global__ void __launch_bounds__(256, 1) fused_kernel(const float* __restrict__ A,
                                                       const float* __restrict__ WihF,
                                                       const float* __restrict__ WihB) {
    extern __shared__ float smdyn[];

    if (blockIdx.x >= 32) {
        // =========================== GEMM path (unchanged) ===========================
        float* As = smdyn;               // [128*36]
        float* Bs = smdyn + 128 * 36;    // [128*36]
        int bid2 = blockIdx.x - 32;
        int gx = bid2 & 15;
        int gy = bid2 >> 4;            // 0..63
        int pos = gy >> 2;             // 0..15 position in chunk order
        int tb  = gy & 3;              // batch group: b in [tb*8, tb*8+8)
        int chunk = (pos & 1) ? (15 - (pos >> 1)) : (pos >> 1);

        int tid  = threadIdx.x;
        int lane = tid & 31;
        int warp = tid >> 5;
        int wm = warp >> 2;            // 0..1
        int wn = warp & 3;             // 0..3
        int nBase = gx * 128;

        int lrow = tid >> 3;           // 0..31
        int lq   = tid & 7;            // 0..7 -> col lq*4

        const float* aPtr[4];
        const float* bPtr[4];
        #pragma unroll
        for (int p = 0; p < 4; ++p) {
            int r  = lrow + p * 32;
            int rb = tb * 8 + (r & 7);
            int rs = chunk * 16 + (r >> 3);
            aPtr[p] = A + (size_t)(rb * 256 + rs) * DW + lq * 4;
            int n = nBase + r;
            const float* W = (n >= G4) ? WihB : WihF;
            bPtr[p] = W + (size_t)(n & 1023) * WIH_STRIDE + lq * 4;
        }

        float acc[4][4][4];
        #pragma unroll
        for (int mt = 0; mt < 4; ++mt)
            #pragma unroll
            for (int nt = 0; nt < 4; ++nt)
                #pragma unroll
                for (int q = 0; q < 4; ++q) acc[mt][nt][q] = 0.f;

        float4 ra[4], rb4[4];
        #pragma unroll
        for (int p = 0; p < 4; ++p) {
            ra[p]  = *(const float4*)aPtr[p];
            rb4[p] = *(const float4*)bPtr[p];
        }

        for (int kt = 0; kt < DW; kt += 32) {
            if (kt) __syncthreads();
            #pragma unroll
            for (int p = 0; p < 4; ++p) {
                int r = lrow + p * 32;
                *(float4*)&As[r * 36 + lq * 4] = tf4(ra[p]);
                *(float4*)&Bs[r * 36 + lq * 4] = tf4(rb4[p]);
            }
            __syncthreads();
            if (kt + 32 < DW) {
                #pragma unroll
                for (int p = 0; p < 4; ++p) {
                    ra[p]  = *(const float4*)(aPtr[p] + kt + 32);
                    rb4[p] = *(const float4*)(bPtr[p] + kt + 32);
                }
            }
            int q  = lane & 3;
            int gp = lane >> 2;
            #pragma unroll
            for (int kc = 0; kc < 32; kc += 8) {
                unsigned afr[4][4], bfr[4][2];
                #pragma unroll
                for (int mt = 0; mt < 4; ++mt) {
                    int r = wm * 64 + mt * 16 + gp;
                    afr[mt][0] = __float_as_uint(As[r * 36 + kc + q]);
                    afr[mt][1] = __float_as_uint(As[(r + 8) * 36 + kc + q]);
                    afr[mt][2] = __float_as_uint(As[r * 36 + kc + q + 4]);
                    afr[mt][3] = __float_as_uint(As[(r + 8) * 36 + kc + q + 4]);
                }
                #pragma unroll
                for (int nt = 0; nt < 4; ++nt) {
                    int c = wn * 32 + nt * 8 + gp;
                    bfr[nt][0] = __float_as_uint(Bs[c * 36 + kc + q]);
                    bfr[nt][1] = __float_as_uint(Bs[c * 36 + kc + q + 4]);
                }
                #pragma unroll
                for (int mt = 0; mt < 4; ++mt)
                    #pragma unroll
                    for (int nt = 0; nt < 4; ++nt)
                        mma_tf32(acc[mt][nt], afr[mt], bfr[nt]);
            }
        }

        #pragma unroll
        for (int mt = 0; mt < 4; ++mt) {
            int base = wm * 64 + mt * 16;
            int s0 = chunk * 16 + (base >> 3);
            int bb = tb * 8 + (lane >> 2);
            float v0 = g_v[bb * 256 + s0];
            float v1 = g_v[bb * 256 + s0 + 1];
            #pragma unroll
            for (int nt = 0; nt < 4; ++nt) {
                int n0  = nBase + wn * 32 + nt * 8 + 2 * (lane & 3);
                int dir = n0 >> 10;
                int g   = n0 & 1023;
                float2 w2  = *(const float2*)&g_wsum[n0];
                float2 bi2 = *(const float2*)&g_bias[n0];
                size_t base0 = (((size_t)dir * SS + s0) * BB + bb) * G4 + g;
                float2 o0 = make_float2(acc[mt][nt][0] + v0 * w2.x + bi2.x,
                                        acc[mt][nt][1] + v0 * w2.y + bi2.y);
                *(float2*)&g_pre[base0] = o0;
                size_t base1 = (((size_t)dir * SS + (s0 + 1)) * BB + bb) * G4 + g;
                float2 o1 = make_float2(acc[mt][nt][2] + v1 * w2.x + bi2.x,
                                        acc[mt][nt][3] + v1 * w2.y + bi2.y);
                *(float2*)&g_pre[base1] = o1;
            }
        }

        __syncthreads();
        if (tid == 0) redrel(&g_chunkcnt[chunk * 32], 1u);
        return;
    }

    // =========================== LSTM path ===========================
    float* smB  = smdyn;            // [16 ntL][32 kt][32 lane][2] = 32768 floats
    float* slab = smdyn + 32768;    // per-warp [16 col][17] gather

    int bid = blockIdx.x;
    int dir = bid >> 4;
    int bs  = (bid >> 3) & 1;
    int js  = bid & 7;
    int tid = threadIdx.x;
    int lane = tid & 31;
    int w    = tid >> 5;

    // ---- Whh B-fragments -> smem, frag-ordered (loaded once) ----
    {
        const float* Wt = g_wt + (size_t)dir * G4 * HH;
        for (int idx = tid; idx < 32768; idx += 256) {
            int h  = idx & 1;
            int ln = (idx >> 1) & 31;
            int kt = (idx >> 6) & 31;
            int ntL = idx >> 11;
            int n = js * 128 + ntL * 8 + (ln >> 2);
            int k = kt * 8 + (ln & 3) + h * 4;
            smB[idx] = Wt[(size_t)n * HH + k];
        }
    }
    __syncthreads();

    // ---- cell identity: warp w owns j in [js*32 + w*4, +4); lane (p, rloc) ----
    int p    = lane & 3;
    int rloc = lane >> 2;           // 0..7
    int j    = js * 32 + w * 4 + p;
    int b0   = bs * 16 + rloc;
    int b1   = b0 + 8;

    // publish addresses (validated fragment formula; lane_s == lane here)
    int ktp   = js * 4 + (w >> 1);
    int word0 = ktp * 128 + lane * 4 + ((w & 1) << 1);

    const float* preD = g_pre + (size_t)dir * SS * BB * G4;
    float* stageD = g_hfrag2 + (size_t)(dir * 2 + bs) * 2 * 4096;
    unsigned* myfl = &g_flag3[dir][bs][js][0];
    const unsigned* srcfl = &g_flag3[dir][bs][lane & 7][0];
    float* myslab = slab + w * 272;
    const float2* smB2 = (const float2*)smB;

    float c0 = 0.f, c1 = 0.f;
    float pr[8];
    {
        int t0 = dir ? (SS - 1) : 0;
        chunk_wait(t0 >> 4);
        const float* pp0 = preD + ((size_t)t0 * BB + b0) * G4;
        const float* pp1 = preD + ((size_t)t0 * BB + b1) * G4;
        #pragma unroll
        for (int g = 0; g < 4; ++g) { pr[g] = pp0[g * 256 + j]; pr[4 + g] = pp1[g * 256 + j]; }
    }

    for (int ts = 0; ts < SS; ++ts) {
        int t  = dir ? (SS - 1 - ts) : ts;
        int tn = dir ? (SS - 2 - ts) : (ts + 1);

        // gate next GEMM chunk (once per 16 steps), then prefetch next pre
        if (ts + 1 < SS && (ts & 15) == 15) chunk_wait(tn >> 4);
        float np[8];
        if (ts + 1 < SS) {
            const float* pn0 = preD + ((size_t)tn * BB + b0) * G4;
            const float* pn1 = preD + ((size_t)tn * BB + b1) * G4;
            #pragma unroll
            for (int g = 0; g < 4; ++g) { np[g] = pn0[g * 256 + j]; np[4 + g] = pn1[g * 256 + j]; }
        }

        float acc[2][4];
        #pragma unroll
        for (int nt = 0; nt < 2; ++nt)
            #pragma unroll
            for (int q = 0; q < 4; ++q) acc[nt][q] = 0.f;

        if (ts > 0) {
            // warp-autonomous wait on the 8 producer CTAs of this (dir,bs) group
            unsigned tg = (unsigned)ts;
            for (;;) {
                bool ok = true;
                if (lane < 8) ok = (ldacq(srcfl) >= tg);
                if (__ballot_sync(0xffffffffu, ok) == 0xffffffffu) break;
            }
            // matvec: full K=256, M=16, N=16 per warp
            const float4* hf = (const float4*)(stageD + (ts & 1) * 4096);
            #pragma unroll
            for (int kt = 0; kt < 32; ++kt) {
                float4 a = __ldcg(hf + kt * 32 + lane);
                unsigned ar[4] = {__float_as_uint(a.x), __float_as_uint(a.y),
                                  __float_as_uint(a.z), __float_as_uint(a.w)};
                float2 bb0 = smB2[((w * 2 + 0) * 32 + kt) * 32 + lane];
                float2 bb1 = smB2[((w * 2 + 1) * 32 + kt) * 32 + lane];
                unsigned br0[2] = {__float_as_uint(bb0.x), __float_as_uint(bb0.y)};
                unsigned br1[2] = {__float_as_uint(bb1.x), __float_as_uint(bb1.y)};
                mma_tf32(acc[0], ar, br0);
                mma_tf32(acc[1], ar, br1);
            }
        }

        // per-warp gate gather (C-fragment -> cells), no block sync
        #pragma unroll
        for (int nt = 0; nt < 2; ++nt)
            #pragma unroll
            for (int q = 0; q < 4; ++q) {
                int col = nt * 8 + ((lane & 3) << 1) + (q & 1);
                int row = (lane >> 2) + ((q & 2) ? 8 : 0);
                myslab[col * 17 + row] = acc[nt][q];
            }
        __syncwarp();

        float h0, h1;
        {
            float g0 = myslab[(p * 4 + 0) * 17 + rloc] + pr[0];
            float g1 = myslab[(p * 4 + 1) * 17 + rloc] + pr[1];
            float g2 = myslab[(p * 4 + 2) * 17 + rloc] + pr[2];
            float g3 = myslab[(p * 4 + 3) * 17 + rloc] + pr[3];
            c0 = sigmoidf_(g1) * c0 + sigmoidf_(g0) * tanh_fast(g2);
            h0 = sigmoidf_(g3) * tanh_fast(c0);
        }
        {
            float g0 = myslab[(p * 4 + 0) * 17 + rloc + 8] + pr[4];
            float g1 = myslab[(p * 4 + 1) * 17 + rloc + 8] + pr[5];
            float g2 = myslab[(p * 4 + 2) * 17 + rloc + 8] + pr[6];
            float g3 = myslab[(p * 4 + 3) * 17 + rloc + 8] + pr[7];
            c1 = sigmoidf_(g1) * c1 + sigmoidf_(g0) * tanh_fast(g2);
            h1 = sigmoidf_(g3) * tanh_fast(c1);
        }

        // publish h fragments (critical path)
        float* hw = stageD + ((ts + 1) & 1) * 4096;
        hw[word0]     = __uint_as_float(f2tf(h0));
        hw[word0 + 1] = __uint_as_float(f2tf(h1));

        __syncthreads();                 // all warps' publishes issued before release
        if (tid == 0) strel(myfl, (unsigned)(ts + 1));

        // off-critical-path: g_hs for emissions
        g_hs[(((size_t)dir * SS + t) * BB + b0) * HH + j] = h0;
        g_hs[(((size_t)dir * SS + t) * BB + b1) * HH + j] = h1;

        #pragma unroll
        for (int g = 0; g < 8; ++g) pr[g] = np[g];
    }
}

// ---------------- kernel 5: emissions + NLL partial sums ----------------
__global__ void __launch_bounds__(256) emis_kernel(const int* __restrict__ labels,
                                                   const float* __restrict__ Wtag,
                                                   const float* __restrict__ btag) {
    __shared__ float wt[NTAG * 512];
    __shared__ float bt[NTAG];
    int tid = threadIdx.x;
    for (int i = tid; i < NTAG * 512; i += 256) wt[i] = Wtag[i];
    if (tid < NTAG) bt[tid] = btag[tid];
    __syncthreads();

    int idx = blockIdx.x * 256 + tid;      // 0..8191
    int b = idx >> 8, t = idx & 255;

    float acc[NTAG];
    #pragma unroll
    for (int q = 0; q < NTAG; ++q) acc[q] = bt[q];

    #pragma unroll
    for (int part = 0; part < 2; ++part) {
        const float* hp = g_hs + (((size_t)part * SS + t) * BB + b) * HH;
        for (int k4 = 0; k4 < HH; k4 += 4) {
            float4 h4 = *(const float4*)&hp[k4];
            #pragma unroll
            for (int q = 0; q < NTAG; ++q) {
                const float* w = &wt[q * 512 + part * HH + k4];
                acc[q] += h4.x * w[0] + h4.y * w[1] + h4.z * w[2] + h4.w * w[3];
            }
        }
    }

    int lab = labels[idx];
    float nll = 0.f, cnt = 0.f;
    if (lab != -100) {
        int lc = lab < 0 ? 0 : lab;
        float m = acc[0];
        #pragma unroll
        for (int q = 1; q < NTAG; ++q) m = fmaxf(m, acc[q]);
        float s = 0.f;
        #pragma unroll
        for (int q = 0; q < NTAG; ++q) s += __expf(acc[q] - m);
        nll = m + logf(s) - acc[lc];
        cnt = 1.f;
    }
    #pragma unroll
    for (int off = 16; off; off >>= 1) {
        nll += __shfl_xor_sync(0xffffffffu, nll, off);
        cnt += __shfl_xor_sync(0xffffffffu, cnt, off);
    }
    if ((tid & 31) == 0) {
        atomicAdd(&g_loss_sum, nll);
        atomicAdd(&g_loss_cnt, cnt);
    }
}

// ---------------- kernel 6: finalize ----------------
__global__ void finalize_kernel(float* out) {
    out[0] = g_loss_sum / fmaxf(g_loss_cnt, 1.f);
}

// ---------------- launch ----------------
extern "C" void kernel_launch(void* const* d_in, const int* in_sizes, int n_in,
                              void* d_out, int out_size) {
    const float* word_embs = (const float*)d_in[0];
    const float* char_embs = (const float*)d_in[1];
    const int*   spans     = (const int*)  d_in[2];
    const int*   labels    = (const int*)  d_in[3];
    const float* WihF      = (const float*)d_in[4];
    const float* WhhF      = (const float*)d_in[5];
    const float* bihF      = (const float*)d_in[6];
    const float* bhhF      = (const float*)d_in[7];
    const float* WihB      = (const float*)d_in[8];
    const float* WhhB      = (const float*)d_in[9];
    const float* bihB      = (const float*)d_in[10];
    const float* bhhB      = (const float*)d_in[11];
    const float* Wtag      = (const float*)d_in[12];
    const float* btag      = (const float*)d_in[13];
    float* out = (float*)d_out;

    cudaFuncSetAttribute(fused_kernel, cudaFuncAttributeMaxDynamicSharedMemorySize, FUSED_SMEM_BYTES);

    prep_v_kernel<<<1024, 256>>>(char_embs, spans);
    prep_w_kernel<<<256, 256>>>(WihF, WihB, bihF, bhhF, bihB, bhhB);
    prep_wt_kernel<<<2048, 256>>>(WhhF, WhhB);
    fused_kernel<<<1056, 256, FUSED_SMEM_BYTES>>>(word_embs, WihF, WihB);
    emis_kernel<<<32, 256>>>(labels, Wtag, btag);
    finalize_kernel<<<1, 1>>>(out);
}